// round 4
// baseline (speedup 1.0000x reference)
#include <cuda_runtime.h>
#include <math.h>

// ---------------- problem constants ----------------
constexpr int BH   = 64;      // b*h = 2*32
constexpr int S    = 8192;
constexpr int D    = 128;
constexpr int SLOC = 64;
constexpr int SEARCH = S - SLOC;      // 8128
constexpr int KTOP = 192;             // KEEP_HH - LOCAL_LEN
constexpr int KEEP = 256;             // KEEP_HH
constexpr int SP   = S - KEEP;        // 7936
constexpr int MC   = 256;             // MEM_COMPRESS
constexpr int C0I  = 256, C0O = 512, K0 = 768;
constexpr int C1I  = 512, C1O = 256, K1 = 1536;
constexpr int XS   = 7940;            // padded length: col = t+1, pads at 0 and SP+1
constexpr size_t VOFF = (size_t)BH * 512 * 128;   // values offset in d_out

// ---------------- device scratch (static; no allocation allowed) ----------------
__device__ int   g_hhpos[BH * KEEP];
__device__ int   g_nonpos[BH * SP];
__device__ int   g_rpos[BH * MC];
__device__ float g_x [(size_t)BH * C0I * XS];   // conv0 input, channel-major, padded
__device__ float g_h0[(size_t)BH * C1I * XS];   // conv0 output (silu), padded
__device__ float g_p [(size_t)BH * MC  * SP];   // conv1 out -> logits -> probs
__device__ float g_w0r[C0O * K0];               // reordered weights k = r*CIN + i
__device__ float g_w1r[C1O * K1];

// ---------------- helpers ----------------
__device__ __forceinline__ unsigned f2key(float f) {
    unsigned u = __float_as_uint(f);
    return (u & 0x80000000u) ? ~u : (u | 0x80000000u);
}

// exclusive scan over 256 threads; returns exclusive prefix, writes total
__device__ int blk_scan_excl(int v, int& total) {
    __shared__ int wsum[8];
    __shared__ int tot;
    int tid = threadIdx.x, lane = tid & 31, w = tid >> 5;
    __syncthreads();              // protect shared reuse across calls
    int incl = v;
#pragma unroll
    for (int o = 1; o < 32; o <<= 1) {
        int y = __shfl_up_sync(0xffffffffu, incl, o);
        if (lane >= o) incl += y;
    }
    if (lane == 31) wsum[w] = incl;
    __syncthreads();
    if (tid == 0) {
        int run = 0;
#pragma unroll
        for (int i = 0; i < 8; i++) { int t = wsum[i]; wsum[i] = run; run += t; }
        tot = run;
    }
    __syncthreads();
    total = tot;
    return wsum[w] + incl - v;
}

// exact radix top-k threshold: after return, #(key > T) = k - tieNeed,
// and the selected set = {key > T} plus first tieNeed elements with key == T
// in ascending index order (matches jax.lax.top_k stable tie semantics).
__device__ void radix_topk(const float* __restrict__ sc, const int* __restrict__ idxmap,
                           int n, int k, unsigned& T, int& tieNeed) {
    __shared__ unsigned hist[256];
    __shared__ unsigned sh_pref;
    __shared__ int      sh_need;
    int tid = threadIdx.x;
    unsigned pref = 0; int need = k;
    for (int shift = 24; shift >= 0; shift -= 8) {
        __syncthreads();
        hist[tid] = 0;
        __syncthreads();
        for (int i = tid; i < n; i += 256) {
            int idx = idxmap ? idxmap[i] : i;
            unsigned key = f2key(sc[idx]);
            unsigned long long hi = (unsigned long long)key  >> (shift + 8);
            unsigned long long ph = (unsigned long long)pref >> (shift + 8);
            if (hi == ph) atomicAdd(&hist[(key >> shift) & 255], 1u);
        }
        __syncthreads();
        if (tid == 0) {
            unsigned cum = 0; int b = 255;
            for (; b > 0; b--) { unsigned h = hist[b]; if (cum + h >= (unsigned)need) break; cum += h; }
            // safety: if loop fell through to b==0 it is the answer bucket by invariant
            unsigned h0v = hist[b];
            (void)h0v;
            sh_pref = pref | ((unsigned)b << shift);
            // recompute cum excluding chosen bucket (cum already excludes it)
            sh_need = need - (int)cum;
        }
        __syncthreads();
        pref = sh_pref; need = sh_need;
    }
    T = pref; tieNeed = need;
}

// ---------------- kernel 1: weight reorder ----------------
__global__ void k_wprep(const float* __restrict__ w0, const float* __restrict__ w1) {
    int n0 = C0O * K0, n1 = C1O * K1;
    for (int e = blockIdx.x * blockDim.x + threadIdx.x; e < n0 + n1; e += gridDim.x * blockDim.x) {
        if (e < n0) {
            int o = e / K0, k = e % K0, r = k / C0I, i = k % C0I;
            g_w0r[e] = w0[(o * C0I + i) * 3 + r];
        } else {
            int e2 = e - n0;
            int o = e2 / K1, k = e2 % K1, r = k / C1I, i = k % C1I;
            g_w1r[e2] = w1[(o * C1I + i) * 3 + r];
        }
    }
}

// ---------------- kernel 2: zero conv pads ----------------
__global__ void k_zeropad() {
    int tot = BH * C1I;
    for (int e = blockIdx.x * blockDim.x + threadIdx.x; e < tot; e += gridDim.x * blockDim.x) {
        int bh = e / C1I, c = e % C1I;
        size_t b0 = ((size_t)bh * C1I + c) * XS;
        g_h0[b0] = 0.f; g_h0[b0 + SP + 1] = 0.f;
        if (c < C0I) {
            size_t b1 = ((size_t)bh * C0I + c) * XS;
            g_x[b1] = 0.f; g_x[b1 + SP + 1] = 0.f;
        }
    }
}

// ---------------- kernel 3: exact selection (both top-k's) ----------------
__global__ void __launch_bounds__(256) k_select(const float* __restrict__ scores) {
    int bh = blockIdx.x, tid = threadIdx.x;
    const float* sc = scores + (size_t)bh * S;

    // ---- Part A: top-KTOP over [0, SEARCH) ----
    unsigned T; int tieNeed;
    radix_topk(sc, nullptr, SEARCH, KTOP, T, tieNeed);

    int base = tid * 32;
    int eqc = 0;
    for (int j = 0; j < 32; j++) {
        int i = base + j;
        if (i < SEARCH && f2key(sc[i]) == T) eqc++;
    }
    int eqTot; int eqBase = blk_scan_excl(eqc, eqTot);
    unsigned mw = 0;
    {
        int run = eqBase;
        for (int j = 0; j < 32; j++) {
            int i = base + j;
            if (i >= SEARCH) { mw |= 1u << j; }          // last LOCAL_LEN always kept
            else {
                unsigned key = f2key(sc[i]);
                if (key > T) mw |= 1u << j;
                else if (key == T) { if (run < tieNeed) mw |= 1u << j; run++; }
            }
        }
    }
    int selTot; int selBase = blk_scan_excl(__popc(mw), selTot);
    {
        int sr = selBase, nr = base - selBase;
        for (int j = 0; j < 32; j++) {
            int i = base + j;
            if ((mw >> j) & 1u) g_hhpos[bh * KEEP + (sr++)] = i;
            else                g_nonpos[bh * SP   + (nr++)] = i;
        }
    }
    __syncthreads();   // g_nonpos visible to block

    // ---- Part E: top-MC over non positions ----
    const int* npos = g_nonpos + bh * SP;
    unsigned T2; int tie2;
    radix_topk(sc, npos, SP, MC, T2, tie2);

    int eqc2 = 0;
    if (tid < SP / 32) {
        for (int j = 0; j < 32; j++) {
            int s = tid * 32 + j;
            if (f2key(sc[npos[s]]) == T2) eqc2++;
        }
    }
    int eqTot2; int eqB2 = blk_scan_excl(eqc2, eqTot2);
    unsigned mw2 = 0;
    if (tid < SP / 32) {
        int run2 = eqB2;
        for (int j = 0; j < 32; j++) {
            int s = tid * 32 + j;
            unsigned key = f2key(sc[npos[s]]);
            if (key > T2) mw2 |= 1u << j;
            else if (key == T2) { if (run2 < tie2) mw2 |= 1u << j; run2++; }
        }
    }
    int selTot2; int sb2 = blk_scan_excl(__popc(mw2), selTot2);
    if (tid < SP / 32) {
        int rr = sb2;
        for (int j = 0; j < 32; j++) {
            if ((mw2 >> j) & 1u) g_rpos[bh * MC + (rr++)] = npos[tid * 32 + j];
        }
    }
}

// ---------------- kernel 4: gather + transpose into conv input ----------------
__global__ void __launch_bounds__(256) k_gather_x(const float* __restrict__ Kin,
                                                  const float* __restrict__ Vin) {
    __shared__ float tile[32][257];
    __shared__ int   pos[32];
    int bh = blockIdx.y, t0 = blockIdx.x * 32, tid = threadIdx.x;
    if (tid < 32) pos[tid] = g_nonpos[bh * SP + t0 + tid];
    __syncthreads();
    const float* Kb = Kin + (size_t)bh * S * D;
    const float* Vb = Vin + (size_t)bh * S * D;
    int d = tid & 127, half = tid >> 7;
    const float* src = half ? Vb : Kb;
#pragma unroll 4
    for (int tt = 0; tt < 32; tt++)
        tile[tt][half * 128 + d] = src[(size_t)pos[tt] * D + d];
    __syncthreads();
    int t = tid & 31, cb = tid >> 5;
    float* Xb = g_x + (size_t)bh * C0I * XS;
#pragma unroll 8
    for (int c = cb; c < C0I; c += 8)
        Xb[(size_t)c * XS + 1 + t0 + t] = tile[t][c];
}

// ---------------- kernel 5/6: conv-as-SGEMM (128x128x8, silu epilogue) ----------------
template <int CIN>
__global__ void __launch_bounds__(256) k_conv(const float* __restrict__ bias,
                                              int M, int K, int yStride, int yColOff) {
    constexpr int LOG = (CIN == 256) ? 8 : 9;
    const float* A = (CIN == 256) ? g_w0r : g_w1r;
    const float* X = (CIN == 256) ? g_x   : g_h0;
    float*       Y = (CIN == 256) ? g_h0  : g_p;

    __shared__ float As[8][128];
    __shared__ float Bs[8][132];
    int tid = threadIdx.x, tx = tid & 15, ty = tid >> 4;
    int n0 = blockIdx.x * 128, m0 = blockIdx.y * 128, bh = blockIdx.z;
    const float* Xb = X + (size_t)bh * CIN * XS;

    float acc[8][8] = {};
    int kkB = tid >> 5, nnB = tid & 31;

    for (int kt = 0; kt < K; kt += 8) {
#pragma unroll
        for (int q = 0; q < 4; q++) {
            int e = tid + q * 256; int m = e >> 3, kk = e & 7;
            As[kk][m] = A[(size_t)(m0 + m) * K + kt + kk];
        }
        {
            int k = kt + kkB; int ci = k & (CIN - 1); int r = k >> LOG;
            const float* src = Xb + (size_t)ci * XS + r + n0;
#pragma unroll
            for (int q = 0; q < 4; q++) Bs[kkB][nnB + q * 32] = src[nnB + q * 32];
        }
        __syncthreads();
#pragma unroll
        for (int kk = 0; kk < 8; kk++) {
            float a[8], b[8];
#pragma unroll
            for (int i = 0; i < 8; i++) a[i] = As[kk][ty * 8 + i];
#pragma unroll
            for (int j = 0; j < 8; j++) b[j] = Bs[kk][tx * 8 + j];
#pragma unroll
            for (int i = 0; i < 8; i++)
#pragma unroll
                for (int j = 0; j < 8; j++) acc[i][j] = fmaf(a[i], b[j], acc[i][j]);
        }
        __syncthreads();
    }
    float* Yb = Y + (size_t)bh * (size_t)M * yStride;
#pragma unroll
    for (int i = 0; i < 8; i++) {
        int m = m0 + ty * 8 + i; float bb = bias[m];
#pragma unroll
        for (int j = 0; j < 8; j++) {
            int n = n0 + tx * 8 + j;
            float v = acc[i][j] + bb;
            v = v * (1.f / (1.f + __expf(-v)));        // silu
            Yb[(size_t)m * yStride + yColOff + n] = v;
        }
    }
}

// ---------------- kernel 7: row softmax over SP ----------------
__device__ float blk_max256(float v) {
    __shared__ float sh[8]; __shared__ float res;
    int tid = threadIdx.x;
    __syncthreads();
#pragma unroll
    for (int o = 16; o; o >>= 1) v = fmaxf(v, __shfl_xor_sync(0xffffffffu, v, o));
    if ((tid & 31) == 0) sh[tid >> 5] = v;
    __syncthreads();
    if (tid == 0) { float m = sh[0]; for (int i = 1; i < 8; i++) m = fmaxf(m, sh[i]); res = m; }
    __syncthreads();
    return res;
}
__device__ float blk_sum256(float v) {
    __shared__ float sh[8]; __shared__ float res;
    int tid = threadIdx.x;
    __syncthreads();
#pragma unroll
    for (int o = 16; o; o >>= 1) v += __shfl_xor_sync(0xffffffffu, v, o);
    if ((tid & 31) == 0) sh[tid >> 5] = v;
    __syncthreads();
    if (tid == 0) { float s = 0; for (int i = 0; i < 8; i++) s += sh[i]; res = s; }
    __syncthreads();
    return res;
}

__global__ void __launch_bounds__(256) k_softmax() {
    int bh = blockIdx.y, m = blockIdx.x, tid = threadIdx.x;
    float* row = g_p + ((size_t)bh * MC + m) * SP;
    float v[31]; float mx = -1e30f;
#pragma unroll
    for (int q = 0; q < 31; q++) { v[q] = row[tid + q * 256]; mx = fmaxf(mx, v[q]); }
    mx = blk_max256(mx);
    float s = 0.f;
#pragma unroll
    for (int q = 0; q < 31; q++) { float e = __expf(v[q] - mx); v[q] = e; s += e; }
    s = blk_sum256(s);
    float inv = 1.f / s;
#pragma unroll
    for (int q = 0; q < 31; q++) row[tid + q * 256] = v[q] * inv;
}

// ---------------- kernel 8: merged = n * (P @ non_kv) + (1-n) * kv[rpos] ----------------
__global__ void __launch_bounds__(256) k_merge(const float* __restrict__ Kin,
                                               const float* __restrict__ Vin,
                                               const float* __restrict__ nrm_ptr,
                                               float* __restrict__ out) {
    int which = blockIdx.x, mt = blockIdx.y, bh = blockIdx.z, tid = threadIdx.x;
    int tx = tid & 15, ty = tid >> 4;
    const float* SRC = (which ? Vin : Kin) + (size_t)bh * S * D;
    const float* P   = g_p + ((size_t)bh * MC + mt * 128) * SP;
    const int*   npos = g_nonpos + bh * SP;

    __shared__ float Ps[16][132];
    __shared__ float Ks[16][128];
    __shared__ int   spos[16];

    float acc[8][8] = {};
    for (int st = 0; st < SP; st += 16) {
        if (tid < 16) spos[tid] = npos[st + tid];
        __syncthreads();
#pragma unroll
        for (int q = 0; q < 8; q++) {
            int e = tid + q * 256; int mI = e >> 4, ss = e & 15;
            Ps[ss][mI] = P[(size_t)mI * SP + st + ss];
        }
#pragma unroll
        for (int q = 0; q < 8; q++) {
            int e = tid + q * 256; int ss = e >> 7, d = e & 127;
            Ks[ss][d] = SRC[(size_t)spos[ss] * D + d];
        }
        __syncthreads();
#pragma unroll
        for (int kk = 0; kk < 16; kk++) {
            float a[8], b[8];
#pragma unroll
            for (int i = 0; i < 8; i++) a[i] = Ps[kk][ty * 8 + i];
#pragma unroll
            for (int j = 0; j < 8; j++) b[j] = Ks[kk][tx * 8 + j];
#pragma unroll
            for (int i = 0; i < 8; i++)
#pragma unroll
                for (int j = 0; j < 8; j++) acc[i][j] = fmaf(a[i], b[j], acc[i][j]);
        }
        __syncthreads();
    }
    float nrm = nrm_ptr[0], rn = 1.f - nrm;
    float* ob = out + (which ? VOFF : 0) + ((size_t)bh * 512 + 256 + mt * 128) * 128;
#pragma unroll
    for (int i = 0; i < 8; i++) {
        int ml = ty * 8 + i; int mg = mt * 128 + ml;
        int rp = g_rpos[bh * MC + mg];
        const float* rrow = SRC + (size_t)rp * D;
#pragma unroll
        for (int j = 0; j < 8; j++) {
            int d = tx * 8 + j;
            ob[(size_t)ml * 128 + d] = nrm * acc[i][j] + rn * rrow[d];
        }
    }
}

// ---------------- kernel 9: exact hh gather into output rows [0,256) ----------------
__global__ void __launch_bounds__(256) k_hhcopy(const float* __restrict__ Kin,
                                                const float* __restrict__ Vin,
                                                float* __restrict__ out) {
    int bh = blockIdx.x, tid = threadIdx.x;
    const float* Kb = Kin + (size_t)bh * S * D;
    const float* Vb = Vin + (size_t)bh * S * D;
    float* ok = out + (size_t)bh * 512 * 128;
    float* ov = out + VOFF + (size_t)bh * 512 * 128;
    for (int e = tid; e < KEEP * D; e += 256) {
        int j = e >> 7, d = e & 127;
        int pos = g_hhpos[bh * KEEP + j];
        ok[(size_t)j * 128 + d] = Kb[(size_t)pos * D + d];
        ov[(size_t)j * 128 + d] = Vb[(size_t)pos * D + d];
    }
}

// ---------------- launch ----------------
extern "C" void kernel_launch(void* const* d_in, const int* in_sizes, int n_in,
                              void* d_out, int out_size) {
    const float* Kin = (const float*)d_in[0];   // past_key_states
    const float* Vin = (const float*)d_in[1];   // past_value_states
    const float* sc  = (const float*)d_in[2];   // hh_scores
    const float* w0  = (const float*)d_in[3];
    const float* b0  = (const float*)d_in[4];
    const float* w1  = (const float*)d_in[5];
    const float* b1  = (const float*)d_in[6];
    const float* nrm = (const float*)d_in[7];
    float* out = (float*)d_out;
    (void)in_sizes; (void)n_in; (void)out_size;

    k_wprep<<<768, 256>>>(w0, w1);
    k_zeropad<<<128, 256>>>();
    k_select<<<BH, 256>>>(sc);
    {
        dim3 g(SP / 32, BH);
        k_gather_x<<<g, 256>>>(Kin, Vin);
    }
    {
        dim3 g0(SP / 128, C0O / 128, BH);        // 62 x 4 x 64
        k_conv<256><<<g0, 256>>>(b0, C0O, K0, XS, 1);
        dim3 g1(SP / 128, C1O / 128, BH);        // 62 x 2 x 64
        k_conv<512><<<g1, 256>>>(b1, C1O, K1, SP, 0);
    }
    {
        dim3 gs(MC, BH);
        k_softmax<<<gs, 256>>>();
    }
    {
        dim3 gm(2, 2, BH);
        k_merge<<<gm, 256>>>(Kin, Vin, nrm, out);
    }
    k_hhcopy<<<BH, 256>>>(Kin, Vin, out);
}

// round 6
// speedup vs baseline: 3.1632x; 3.1632x over previous
#include <cuda_runtime.h>
#include <math.h>

// ---------------- problem constants ----------------
constexpr int BH   = 64;      // b*h = 2*32
constexpr int S    = 8192;
constexpr int D    = 128;
constexpr int SEARCH = S - 64;        // 8128
constexpr int KTOP = 192;             // KEEP_HH - LOCAL_LEN
constexpr int KEEP = 256;             // KEEP_HH
constexpr int SP   = S - KEEP;        // 7936
constexpr int MC   = 256;             // MEM_COMPRESS
constexpr int C0I  = 256, C0O = 512, K0 = 768;
constexpr int C1I  = 512, C1O = 256, K1 = 1536;
constexpr int XR   = SP + 2;          // token rows incl. zero pads at 0 and SP+1
constexpr size_t VOFF = (size_t)BH * 512 * 128;   // values offset in d_out

// ---------------- device scratch (static; no allocation allowed) ----------------
__device__ int   g_hhpos[BH * KEEP];
__device__ int   g_nonpos[BH * SP];
__device__ int   g_rpos[BH * MC];
__device__ float g_xt [(size_t)BH * XR * C0I];   // token-major gathered [k|v], row t+1
__device__ float g_h0t[(size_t)BH * XR * C1I];   // conv0 out (silu), token-major
__device__ float g_p  [(size_t)BH * MC * SP];    // conv1 logits -> probs, [m][t]
__device__ float g_w0r[C0O * K0];                // weights, k = r*CIN + ci
__device__ float g_w1r[C1O * K1];

// ---------------- helpers ----------------
__device__ __forceinline__ unsigned f2key(float f) {
    unsigned u = __float_as_uint(f);
    return (u & 0x80000000u) ? ~u : (u | 0x80000000u);
}

__device__ int blk_scan_excl(int v, int& total) {
    __shared__ int wsum[8];
    __shared__ int tot;
    int tid = threadIdx.x, lane = tid & 31, w = tid >> 5;
    __syncthreads();
    int incl = v;
#pragma unroll
    for (int o = 1; o < 32; o <<= 1) {
        int y = __shfl_up_sync(0xffffffffu, incl, o);
        if (lane >= o) incl += y;
    }
    if (lane == 31) wsum[w] = incl;
    __syncthreads();
    if (tid == 0) {
        int run = 0;
#pragma unroll
        for (int i = 0; i < 8; i++) { int t = wsum[i]; wsum[i] = run; run += t; }
        tot = run;
    }
    __syncthreads();
    total = tot;
    return wsum[w] + incl - v;
}

__device__ void radix_topk(const float* __restrict__ sc, const int* __restrict__ idxmap,
                           int n, int k, unsigned& T, int& tieNeed) {
    __shared__ unsigned hist[256];
    __shared__ unsigned sh_pref;
    __shared__ int      sh_need;
    int tid = threadIdx.x;
    unsigned pref = 0; int need = k;
    for (int shift = 24; shift >= 0; shift -= 8) {
        __syncthreads();
        hist[tid] = 0;
        __syncthreads();
        for (int i = tid; i < n; i += 256) {
            int idx = idxmap ? idxmap[i] : i;
            unsigned key = f2key(sc[idx]);
            unsigned long long hi = (unsigned long long)key  >> (shift + 8);
            unsigned long long ph = (unsigned long long)pref >> (shift + 8);
            if (hi == ph) atomicAdd(&hist[(key >> shift) & 255], 1u);
        }
        __syncthreads();
        if (tid == 0) {
            unsigned cum = 0; int b = 255;
            for (; b > 0; b--) { unsigned h = hist[b]; if (cum + h >= (unsigned)need) break; cum += h; }
            sh_pref = pref | ((unsigned)b << shift);
            sh_need = need - (int)cum;
        }
        __syncthreads();
        pref = sh_pref; need = sh_need;
    }
    T = pref; tieNeed = need;
}

// ---------------- kernel: weight reorder (k = r*CIN + ci) ----------------
__global__ void k_wprep(const float* __restrict__ w0, const float* __restrict__ w1) {
    int n0 = C0O * K0, n1 = C1O * K1;
    for (int e = blockIdx.x * blockDim.x + threadIdx.x; e < n0 + n1; e += gridDim.x * blockDim.x) {
        if (e < n0) {
            int o = e / K0, k = e % K0, r = k / C0I, i = k % C0I;
            g_w0r[e] = w0[(o * C0I + i) * 3 + r];
        } else {
            int e2 = e - n0;
            int o = e2 / K1, k = e2 % K1, r = k / C1I, i = k % C1I;
            g_w1r[e2] = w1[(o * C1I + i) * 3 + r];
        }
    }
}

// ---------------- kernel: zero conv pad rows ----------------
__global__ void k_zeropad() {
    int stride = gridDim.x * blockDim.x;
    int tid = blockIdx.x * blockDim.x + threadIdx.x;
    for (int e = tid; e < BH * C0I; e += stride) {
        int bh = e / C0I, c = e % C0I;
        g_xt[((size_t)bh * XR + 0) * C0I + c] = 0.f;
        g_xt[((size_t)bh * XR + SP + 1) * C0I + c] = 0.f;
    }
    for (int e = tid; e < BH * C1I; e += stride) {
        int bh = e / C1I, c = e % C1I;
        g_h0t[((size_t)bh * XR + 0) * C1I + c] = 0.f;
        g_h0t[((size_t)bh * XR + SP + 1) * C1I + c] = 0.f;
    }
}

// ---------------- kernel: exact selection (both top-k's) ----------------
__global__ void __launch_bounds__(256) k_select(const float* __restrict__ scores) {
    int bh = blockIdx.x, tid = threadIdx.x;
    const float* sc = scores + (size_t)bh * S;

    unsigned T; int tieNeed;
    radix_topk(sc, nullptr, SEARCH, KTOP, T, tieNeed);

    int base = tid * 32;
    int eqc = 0;
    for (int j = 0; j < 32; j++) {
        int i = base + j;
        if (i < SEARCH && f2key(sc[i]) == T) eqc++;
    }
    int eqTot; int eqBase = blk_scan_excl(eqc, eqTot);
    unsigned mw = 0;
    {
        int run = eqBase;
        for (int j = 0; j < 32; j++) {
            int i = base + j;
            if (i >= SEARCH) { mw |= 1u << j; }
            else {
                unsigned key = f2key(sc[i]);
                if (key > T) mw |= 1u << j;
                else if (key == T) { if (run < tieNeed) mw |= 1u << j; run++; }
            }
        }
    }
    int selTot; int selBase = blk_scan_excl(__popc(mw), selTot);
    {
        int sr = selBase, nr = base - selBase;
        for (int j = 0; j < 32; j++) {
            int i = base + j;
            if ((mw >> j) & 1u) g_hhpos[bh * KEEP + (sr++)] = i;
            else                g_nonpos[bh * SP   + (nr++)] = i;
        }
    }
    __syncthreads();

    const int* npos = g_nonpos + bh * SP;
    unsigned T2; int tie2;
    radix_topk(sc, npos, SP, MC, T2, tie2);

    int eqc2 = 0;
    if (tid < SP / 32) {
        for (int j = 0; j < 32; j++) {
            int s = tid * 32 + j;
            if (f2key(sc[npos[s]]) == T2) eqc2++;
        }
    }
    int eqTot2; int eqB2 = blk_scan_excl(eqc2, eqTot2);
    unsigned mw2 = 0;
    if (tid < SP / 32) {
        int run2 = eqB2;
        for (int j = 0; j < 32; j++) {
            int s = tid * 32 + j;
            unsigned key = f2key(sc[npos[s]]);
            if (key > T2) mw2 |= 1u << j;
            else if (key == T2) { if (run2 < tie2) mw2 |= 1u << j; run2++; }
        }
    }
    int selTot2; int sb2 = blk_scan_excl(__popc(mw2), selTot2);
    if (tid < SP / 32) {
        int rr = sb2;
        for (int j = 0; j < 32; j++) {
            if ((mw2 >> j) & 1u) g_rpos[bh * MC + (rr++)] = npos[tid * 32 + j];
        }
    }
}

// ---------------- kernel: coalesced gather into token-major g_xt ----------------
__global__ void __launch_bounds__(256) k_gather(const float* __restrict__ Kin,
                                                const float* __restrict__ Vin) {
    __shared__ int pos[128];
    int bh = blockIdx.y, t0 = blockIdx.x * 128, tid = threadIdx.x;
    if (tid < 128) pos[tid] = g_nonpos[bh * SP + t0 + tid];
    __syncthreads();
    int w = tid >> 5, lane = tid & 31;
    const float4* Kb = (const float4*)(Kin + (size_t)bh * S * D);
    const float4* Vb = (const float4*)(Vin + (size_t)bh * S * D);
    float4* X = (float4*)(g_xt + ((size_t)bh * XR + t0 + 1) * C0I);
    for (int tt = w; tt < 128; tt += 8) {
        int p = pos[tt];
        X[(size_t)tt * 64 + lane]      = Kb[(size_t)p * 32 + lane];
        X[(size_t)tt * 64 + 32 + lane] = Vb[(size_t)p * 32 + lane];
    }
}

// ---------------- tf32 mma helpers ----------------
__device__ __forceinline__ unsigned tf32c(float f) {
    unsigned r; asm("cvt.rna.tf32.f32 %0, %1;" : "=r"(r) : "f"(f)); return r;
}
__device__ __forceinline__ void mma8(float* c, unsigned a0, unsigned a1, unsigned a2, unsigned a3,
                                     unsigned b0, unsigned b1) {
    asm volatile(
        "mma.sync.aligned.m16n8k8.row.col.f32.tf32.tf32.f32 "
        "{%0,%1,%2,%3},{%4,%5,%6,%7},{%8,%9},{%0,%1,%2,%3};\n"
        : "+f"(c[0]), "+f"(c[1]), "+f"(c[2]), "+f"(c[3])
        : "r"(a0), "r"(a1), "r"(a2), "r"(a3), "r"(b0), "r"(b1));
}

// ---------------- conv as TN tensor-core GEMM ----------------
// Y[o][t] = silu( sum_{k=(r,ci)} W[o][k] * X[t+r][ci] + bias[o] )
// A = W [COUT][KTOT] row-major. B row n = token t0+n, k-contiguous across (r,ci).
template <int CIN, int COUT, int KTOT, bool TO_H0>
__global__ void __launch_bounds__(256, 2) k_conv(const float* __restrict__ bias) {
    const float* Wm   = TO_H0 ? g_w0r : g_w1r;
    const float* Xsrc = TO_H0 ? g_xt  : g_h0t;
    float*       Y    = TO_H0 ? g_h0t : g_p;

    __shared__ float As[2][128][20];
    __shared__ float Bs[2][128][20];
    int tid = threadIdx.x;
    int n0 = blockIdx.x * 128, m0 = blockIdx.y * 128, bh = blockIdx.z;
    const float* Xb = Xsrc + (size_t)bh * XR * CIN;
    int w = tid >> 5, lane = tid & 31;
    int wm = (w >> 2) * 64, wn = (w & 3) * 32;

    float acc[4][4][4] = {};
    float4 rA[2], rB[2];

    auto LOAD = [&](int kt) {
#pragma unroll
        for (int q = 0; q < 2; q++) {
            int e = tid + q * 256; int m = e >> 2, kp = (e & 3) * 4;
            rA[q] = *(const float4*)(Wm + (size_t)(m0 + m) * KTOT + kt + kp);
        }
        int r = kt / CIN, ci0 = kt % CIN;
#pragma unroll
        for (int q = 0; q < 2; q++) {
            int e = tid + q * 256; int n = e >> 2, cp = (e & 3) * 4;
            rB[q] = *(const float4*)(Xb + (size_t)(n0 + n + r) * CIN + ci0 + cp);
        }
    };
    auto STORE = [&](int buf) {
#pragma unroll
        for (int q = 0; q < 2; q++) {
            int e = tid + q * 256; int m = e >> 2, kp = (e & 3) * 4;
            float* da = &As[buf][m][kp];
            da[0] = __uint_as_float(tf32c(rA[q].x)); da[1] = __uint_as_float(tf32c(rA[q].y));
            da[2] = __uint_as_float(tf32c(rA[q].z)); da[3] = __uint_as_float(tf32c(rA[q].w));
            float* db = &Bs[buf][m][kp];
            db[0] = __uint_as_float(tf32c(rB[q].x)); db[1] = __uint_as_float(tf32c(rB[q].y));
            db[2] = __uint_as_float(tf32c(rB[q].z)); db[3] = __uint_as_float(tf32c(rB[q].w));
        }
    };
    auto COMP = [&](int buf) {
#pragma unroll
        for (int ks = 0; ks < 16; ks += 8) {
            unsigned a[4][4], b[4][2];
            int c = ks + (lane & 3);
#pragma unroll
            for (int mi = 0; mi < 4; mi++) {
                int row = wm + mi * 16 + (lane >> 2);
                a[mi][0] = __float_as_uint(As[buf][row][c]);
                a[mi][1] = __float_as_uint(As[buf][row + 8][c]);
                a[mi][2] = __float_as_uint(As[buf][row][c + 4]);
                a[mi][3] = __float_as_uint(As[buf][row + 8][c + 4]);
            }
#pragma unroll
            for (int ni = 0; ni < 4; ni++) {
                int col = wn + ni * 8 + (lane >> 2);
                b[ni][0] = __float_as_uint(Bs[buf][col][c]);
                b[ni][1] = __float_as_uint(Bs[buf][col][c + 4]);
            }
#pragma unroll
            for (int mi = 0; mi < 4; mi++)
#pragma unroll
                for (int ni = 0; ni < 4; ni++)
                    mma8(acc[mi][ni], a[mi][0], a[mi][1], a[mi][2], a[mi][3],
                         b[ni][0], b[ni][1]);
        }
    };

    LOAD(0); STORE(0); __syncthreads();
    int buf = 0;
    for (int kt = 16; kt <= KTOT; kt += 16) {
        if (kt < KTOT) LOAD(kt);
        COMP(buf);
        if (kt < KTOT) { STORE(buf ^ 1); __syncthreads(); buf ^= 1; }
    }

#pragma unroll
    for (int mi = 0; mi < 4; mi++)
#pragma unroll
        for (int ni = 0; ni < 4; ni++)
#pragma unroll
            for (int rg = 0; rg < 4; rg++) {
                int ml = wm + mi * 16 + (lane >> 2) + ((rg >> 1) ? 8 : 0);
                int nl = wn + ni * 8 + (lane & 3) * 2 + (rg & 1);
                int m = m0 + ml, t = n0 + nl;
                float v = acc[mi][ni][rg] + bias[m];
                v = v / (1.f + __expf(-v));   // silu
                if (TO_H0) Y[((size_t)bh * XR + t + 1) * COUT + m] = v;
                else       Y[((size_t)bh * COUT + m) * (size_t)SP + t] = v;
            }
}

// ---------------- row softmax over SP ----------------
__device__ float blk_max256(float v) {
    __shared__ float sh[8]; __shared__ float res;
    int tid = threadIdx.x;
    __syncthreads();
#pragma unroll
    for (int o = 16; o; o >>= 1) v = fmaxf(v, __shfl_xor_sync(0xffffffffu, v, o));
    if ((tid & 31) == 0) sh[tid >> 5] = v;
    __syncthreads();
    if (tid == 0) { float m = sh[0]; for (int i = 1; i < 8; i++) m = fmaxf(m, sh[i]); res = m; }
    __syncthreads();
    return res;
}
__device__ float blk_sum256(float v) {
    __shared__ float sh[8]; __shared__ float res;
    int tid = threadIdx.x;
    __syncthreads();
#pragma unroll
    for (int o = 16; o; o >>= 1) v += __shfl_xor_sync(0xffffffffu, v, o);
    if ((tid & 31) == 0) sh[tid >> 5] = v;
    __syncthreads();
    if (tid == 0) { float s = 0; for (int i = 0; i < 8; i++) s += sh[i]; res = s; }
    __syncthreads();
    return res;
}
__global__ void __launch_bounds__(256) k_softmax() {
    int bh = blockIdx.y, m = blockIdx.x, tid = threadIdx.x;
    float* row = g_p + ((size_t)bh * MC + m) * SP;
    float v[31]; float mx = -1e30f;
#pragma unroll
    for (int q = 0; q < 31; q++) { v[q] = row[tid + q * 256]; mx = fmaxf(mx, v[q]); }
    mx = blk_max256(mx);
    float s = 0.f;
#pragma unroll
    for (int q = 0; q < 31; q++) { float e = __expf(v[q] - mx); v[q] = e; s += e; }
    s = blk_sum256(s);
    float inv = 1.f / s;
#pragma unroll
    for (int q = 0; q < 31; q++) row[tid + q * 256] = v[q] * inv;
}

// ---------------- merge: one TN GEMM (256x256xSP) per bh + exact residual ----------------
__global__ void __launch_bounds__(256, 2) k_merge(const float* __restrict__ Kin,
                                                  const float* __restrict__ Vin,
                                                  const float* __restrict__ nrmp,
                                                  float* __restrict__ out) {
    __shared__ float As[2][128][20];
    __shared__ float Bs[2][16][136];
    int tid = threadIdx.x;
    int n0 = blockIdx.x * 128, m0 = blockIdx.y * 128, bh = blockIdx.z;
    const float* A  = g_p + (size_t)bh * MC * SP;
    const float* Xb = g_xt + (size_t)bh * XR * C0I;
    int w = tid >> 5, lane = tid & 31;
    int wm = (w >> 2) * 64, wn = (w & 3) * 32;

    float acc[4][4][4] = {};
    float4 rA[2], rB[2];

    auto LOAD = [&](int kt) {
#pragma unroll
        for (int q = 0; q < 2; q++) {
            int e = tid + q * 256; int m = e >> 2, kp = (e & 3) * 4;
            rA[q] = *(const float4*)(A + (size_t)(m0 + m) * SP + kt + kp);
        }
#pragma unroll
        for (int q = 0; q < 2; q++) {
            int e = tid + q * 256; int k = e >> 5, nc = (e & 31) * 4;
            rB[q] = *(const float4*)(Xb + (size_t)(kt + k + 1) * C0I + n0 + nc);
        }
    };
    auto STORE = [&](int buf) {
#pragma unroll
        for (int q = 0; q < 2; q++) {
            int e = tid + q * 256; int m = e >> 2, kp = (e & 3) * 4;
            float* da = &As[buf][m][kp];
            da[0] = __uint_as_float(tf32c(rA[q].x)); da[1] = __uint_as_float(tf32c(rA[q].y));
            da[2] = __uint_as_float(tf32c(rA[q].z)); da[3] = __uint_as_float(tf32c(rA[q].w));
            int k = e >> 5, nc = (e & 31) * 4;
            float* db = &Bs[buf][k][nc];
            db[0] = __uint_as_float(tf32c(rB[q].x)); db[1] = __uint_as_float(tf32c(rB[q].y));
            db[2] = __uint_as_float(tf32c(rB[q].z)); db[3] = __uint_as_float(tf32c(rB[q].w));
        }
    };
    auto COMP = [&](int buf) {
#pragma unroll
        for (int ks = 0; ks < 16; ks += 8) {
            unsigned a[4][4], b[4][2];
            int c = ks + (lane & 3);
#pragma unroll
            for (int mi = 0; mi < 4; mi++) {
                int row = wm + mi * 16 + (lane >> 2);
                a[mi][0] = __float_as_uint(As[buf][row][c]);
                a[mi][1] = __float_as_uint(As[buf][row + 8][c]);
                a[mi][2] = __float_as_uint(As[buf][row][c + 4]);
                a[mi][3] = __float_as_uint(As[buf][row + 8][c + 4]);
            }
#pragma unroll
            for (int ni = 0; ni < 4; ni++) {
                int col = wn + ni * 8 + (lane >> 2);
                b[ni][0] = __float_as_uint(Bs[buf][c][col]);
                b[ni][1] = __float_as_uint(Bs[buf][c + 4][col]);
            }
#pragma unroll
            for (int mi = 0; mi < 4; mi++)
#pragma unroll
                for (int ni = 0; ni < 4; ni++)
                    mma8(acc[mi][ni], a[mi][0], a[mi][1], a[mi][2], a[mi][3],
                         b[ni][0], b[ni][1]);
        }
    };

    LOAD(0); STORE(0); __syncthreads();
    int buf = 0;
    for (int kt = 16; kt <= SP; kt += 16) {
        if (kt < SP) LOAD(kt);
        COMP(buf);
        if (kt < SP) { STORE(buf ^ 1); __syncthreads(); buf ^= 1; }
    }

    float nrm = nrmp[0], rn = 1.f - nrm;
#pragma unroll
    for (int mi = 0; mi < 4; mi++)
#pragma unroll
        for (int ni = 0; ni < 4; ni++)
#pragma unroll
            for (int rg = 0; rg < 4; rg++) {
                int ml = wm + mi * 16 + (lane >> 2) + ((rg >> 1) ? 8 : 0);
                int nl = wn + ni * 8 + (lane & 3) * 2 + (rg & 1);
                int m = m0 + ml, n = n0 + nl;
                int rp = g_rpos[bh * MC + m];
                float res; float* dst;
                if (n < 128) {
                    res = Kin[((size_t)bh * S + rp) * D + n];
                    dst = out + ((size_t)bh * 512 + 256 + m) * 128 + n;
                } else {
                    res = Vin[((size_t)bh * S + rp) * D + n - 128];
                    dst = out + VOFF + ((size_t)bh * 512 + 256 + m) * 128 + n - 128;
                }
                *dst = nrm * acc[mi][ni][rg] + rn * res;
            }
}

// ---------------- exact hh gather into output rows [0,256) ----------------
__global__ void __launch_bounds__(256) k_hhcopy(const float* __restrict__ Kin,
                                                const float* __restrict__ Vin,
                                                float* __restrict__ out) {
    int bh = blockIdx.x, tid = threadIdx.x;
    const float* Kb = Kin + (size_t)bh * S * D;
    const float* Vb = Vin + (size_t)bh * S * D;
    float* ok = out + (size_t)bh * 512 * 128;
    float* ov = out + VOFF + (size_t)bh * 512 * 128;
    for (int e = tid; e < KEEP * D; e += 256) {
        int j = e >> 7, d = e & 127;
        int pos = g_hhpos[bh * KEEP + j];
        ok[(size_t)j * 128 + d] = Kb[(size_t)pos * D + d];
        ov[(size_t)j * 128 + d] = Vb[(size_t)pos * D + d];
    }
}

// ---------------- launch ----------------
extern "C" void kernel_launch(void* const* d_in, const int* in_sizes, int n_in,
                              void* d_out, int out_size) {
    const float* Kin = (const float*)d_in[0];
    const float* Vin = (const float*)d_in[1];
    const float* sc  = (const float*)d_in[2];
    const float* w0  = (const float*)d_in[3];
    const float* b0  = (const float*)d_in[4];
    const float* w1  = (const float*)d_in[5];
    const float* b1  = (const float*)d_in[6];
    const float* nrm = (const float*)d_in[7];
    float* out = (float*)d_out;
    (void)in_sizes; (void)n_in; (void)out_size;

    k_wprep<<<768, 256>>>(w0, w1);
    k_zeropad<<<128, 256>>>();
    k_select<<<BH, 256>>>(sc);
    {
        dim3 g(SP / 128, BH);
        k_gather<<<g, 256>>>(Kin, Vin);
    }
    {
        dim3 g0(SP / 128, C0O / 128, BH);          // 62 x 4 x 64
        k_conv<C0I, C0O, K0, true><<<g0, 256>>>(b0);
        dim3 g1(SP / 128, C1O / 128, BH);          // 62 x 2 x 64
        k_conv<C1I, C1O, K1, false><<<g1, 256>>>(b1);
    }
    {
        dim3 gs(MC, BH);
        k_softmax<<<gs, 256>>>();
    }
    {
        dim3 gm(2, 2, BH);
        k_merge<<<gm, 256>>>(Kin, Vin, nrm, out);
    }
    k_hhcopy<<<BH, 256>>>(Kin, Vin, out);
}

// round 7
// speedup vs baseline: 6.9339x; 2.1920x over previous
#include <cuda_runtime.h>
#include <cuda_bf16.h>
#include <math.h>

using bf16 = __nv_bfloat16;

// ---------------- problem constants ----------------
constexpr int BH   = 64;      // b*h = 2*32
constexpr int S    = 8192;
constexpr int D    = 128;
constexpr int SEARCH = S - 64;        // 8128
constexpr int KTOP = 192;             // KEEP_HH - LOCAL_LEN
constexpr int KEEP = 256;             // KEEP_HH
constexpr int SP   = S - KEEP;        // 7936
constexpr int MC   = 256;             // MEM_COMPRESS
constexpr int C0I  = 256, C0O = 512, K0 = 768;
constexpr int C1I  = 512, C1O = 256, K1 = 1536;
constexpr int XR   = SP + 2;          // token rows incl. zero pads at 0 and SP+1
constexpr size_t VOFF = (size_t)BH * 512 * 128;   // values offset in d_out

// ---------------- device scratch ----------------
__device__ int  g_hhpos[BH * KEEP];
__device__ int  g_nonpos[BH * SP];
__device__ int  g_rpos[BH * MC];
__device__ bf16 g_xt [(size_t)BH * XR * C0I];   // gathered [k|v] token-major bf16
__device__ bf16 g_h0t[(size_t)BH * XR * C1I];   // conv0 out (silu) token-major bf16
__device__ float g_p [(size_t)BH * MC * SP];    // conv1 logits fp32 [m][t]
__device__ bf16 g_pb [(size_t)BH * MC * SP];    // softmax probs bf16 [m][t]
__device__ bf16 g_w0r[C0O * K0];                // weights bf16, k = r*CIN + ci
__device__ bf16 g_w1r[C1O * K1];

// ---------------- low-level helpers ----------------
#define CP16(dst, src) asm volatile("cp.async.ca.shared.global [%0], [%1], 16;\n" \
    :: "r"((unsigned)__cvta_generic_to_shared(dst)), "l"(src))

__device__ __forceinline__ void ldsm4(unsigned* a, const void* p) {
    unsigned addr = (unsigned)__cvta_generic_to_shared(p);
    asm volatile("ldmatrix.sync.aligned.m8n8.x4.shared.b16 {%0,%1,%2,%3}, [%4];"
                 : "=r"(a[0]), "=r"(a[1]), "=r"(a[2]), "=r"(a[3]) : "r"(addr));
}
__device__ __forceinline__ void ldsm2(unsigned* b, const void* p) {
    unsigned addr = (unsigned)__cvta_generic_to_shared(p);
    asm volatile("ldmatrix.sync.aligned.m8n8.x2.shared.b16 {%0,%1}, [%2];"
                 : "=r"(b[0]), "=r"(b[1]) : "r"(addr));
}
__device__ __forceinline__ void ldsm2t(unsigned* b, const void* p) {
    unsigned addr = (unsigned)__cvta_generic_to_shared(p);
    asm volatile("ldmatrix.sync.aligned.m8n8.x2.trans.shared.b16 {%0,%1}, [%2];"
                 : "=r"(b[0]), "=r"(b[1]) : "r"(addr));
}
__device__ __forceinline__ void mma16(float* c, const unsigned* a, const unsigned* b) {
    asm volatile(
        "mma.sync.aligned.m16n8k16.row.col.f32.bf16.bf16.f32 "
        "{%0,%1,%2,%3},{%4,%5,%6,%7},{%8,%9},{%0,%1,%2,%3};\n"
        : "+f"(c[0]), "+f"(c[1]), "+f"(c[2]), "+f"(c[3])
        : "r"(a[0]), "r"(a[1]), "r"(a[2]), "r"(a[3]), "r"(b[0]), "r"(b[1]));
}

__device__ __forceinline__ unsigned f2key(float f) {
    unsigned u = __float_as_uint(f);
    return (u & 0x80000000u) ? ~u : (u | 0x80000000u);
}

__device__ int blk_scan_excl(int v, int& total) {
    __shared__ int wsum[8];
    __shared__ int tot;
    int tid = threadIdx.x, lane = tid & 31, w = tid >> 5;
    __syncthreads();
    int incl = v;
#pragma unroll
    for (int o = 1; o < 32; o <<= 1) {
        int y = __shfl_up_sync(0xffffffffu, incl, o);
        if (lane >= o) incl += y;
    }
    if (lane == 31) wsum[w] = incl;
    __syncthreads();
    if (tid == 0) {
        int run = 0;
#pragma unroll
        for (int i = 0; i < 8; i++) { int t = wsum[i]; wsum[i] = run; run += t; }
        tot = run;
    }
    __syncthreads();
    total = tot;
    return wsum[w] + incl - v;
}

__device__ void radix_topk(const float* __restrict__ sc, const int* __restrict__ idxmap,
                           int n, int k, unsigned& T, int& tieNeed) {
    __shared__ unsigned hist[256];
    __shared__ unsigned sh_pref;
    __shared__ int      sh_need;
    int tid = threadIdx.x;
    unsigned pref = 0; int need = k;
    for (int shift = 24; shift >= 0; shift -= 8) {
        __syncthreads();
        hist[tid] = 0;
        __syncthreads();
        for (int i = tid; i < n; i += 256) {
            int idx = idxmap ? idxmap[i] : i;
            unsigned key = f2key(sc[idx]);
            unsigned long long hi = (unsigned long long)key  >> (shift + 8);
            unsigned long long ph = (unsigned long long)pref >> (shift + 8);
            if (hi == ph) atomicAdd(&hist[(key >> shift) & 255], 1u);
        }
        __syncthreads();
        if (tid == 0) {
            unsigned cum = 0; int b = 255;
            for (; b > 0; b--) { unsigned h = hist[b]; if (cum + h >= (unsigned)need) break; cum += h; }
            sh_pref = pref | ((unsigned)b << shift);
            sh_need = need - (int)cum;
        }
        __syncthreads();
        pref = sh_pref; need = sh_need;
    }
    T = pref; tieNeed = need;
}

// ---------------- kernel: weight reorder (k = r*CIN + ci), to bf16 ----------------
__global__ void k_wprep(const float* __restrict__ w0, const float* __restrict__ w1) {
    int n0 = C0O * K0, n1 = C1O * K1;
    for (int e = blockIdx.x * blockDim.x + threadIdx.x; e < n0 + n1; e += gridDim.x * blockDim.x) {
        if (e < n0) {
            int o = e / K0, k = e % K0, r = k / C0I, i = k % C0I;
            g_w0r[e] = __float2bfloat16(w0[(o * C0I + i) * 3 + r]);
        } else {
            int e2 = e - n0;
            int o = e2 / K1, k = e2 % K1, r = k / C1I, i = k % C1I;
            g_w1r[e2] = __float2bfloat16(w1[(o * C1I + i) * 3 + r]);
        }
    }
}

// ---------------- kernel: zero conv pad rows ----------------
__global__ void k_zeropad() {
    int stride = gridDim.x * blockDim.x;
    int tid = blockIdx.x * blockDim.x + threadIdx.x;
    bf16 z = __float2bfloat16(0.f);
    for (int e = tid; e < BH * C0I; e += stride) {
        int bh = e / C0I, c = e % C0I;
        g_xt[((size_t)bh * XR + 0) * C0I + c] = z;
        g_xt[((size_t)bh * XR + SP + 1) * C0I + c] = z;
    }
    for (int e = tid; e < BH * C1I; e += stride) {
        int bh = e / C1I, c = e % C1I;
        g_h0t[((size_t)bh * XR + 0) * C1I + c] = z;
        g_h0t[((size_t)bh * XR + SP + 1) * C1I + c] = z;
    }
}

// ---------------- kernel: exact selection (both top-k's) ----------------
__global__ void __launch_bounds__(256) k_select(const float* __restrict__ scores) {
    int bh = blockIdx.x, tid = threadIdx.x;
    const float* sc = scores + (size_t)bh * S;

    unsigned T; int tieNeed;
    radix_topk(sc, nullptr, SEARCH, KTOP, T, tieNeed);

    int base = tid * 32;
    int eqc = 0;
    for (int j = 0; j < 32; j++) {
        int i = base + j;
        if (i < SEARCH && f2key(sc[i]) == T) eqc++;
    }
    int eqTot; int eqBase = blk_scan_excl(eqc, eqTot);
    unsigned mw = 0;
    {
        int run = eqBase;
        for (int j = 0; j < 32; j++) {
            int i = base + j;
            if (i >= SEARCH) { mw |= 1u << j; }
            else {
                unsigned key = f2key(sc[i]);
                if (key > T) mw |= 1u << j;
                else if (key == T) { if (run < tieNeed) mw |= 1u << j; run++; }
            }
        }
    }
    int selTot; int selBase = blk_scan_excl(__popc(mw), selTot);
    {
        int sr = selBase, nr = base - selBase;
        for (int j = 0; j < 32; j++) {
            int i = base + j;
            if ((mw >> j) & 1u) g_hhpos[bh * KEEP + (sr++)] = i;
            else                g_nonpos[bh * SP   + (nr++)] = i;
        }
    }
    __syncthreads();

    const int* npos = g_nonpos + bh * SP;
    unsigned T2; int tie2;
    radix_topk(sc, npos, SP, MC, T2, tie2);

    int eqc2 = 0;
    if (tid < SP / 32) {
        for (int j = 0; j < 32; j++) {
            int s = tid * 32 + j;
            if (f2key(sc[npos[s]]) == T2) eqc2++;
        }
    }
    int eqTot2; int eqB2 = blk_scan_excl(eqc2, eqTot2);
    unsigned mw2 = 0;
    if (tid < SP / 32) {
        int run2 = eqB2;
        for (int j = 0; j < 32; j++) {
            int s = tid * 32 + j;
            unsigned key = f2key(sc[npos[s]]);
            if (key > T2) mw2 |= 1u << j;
            else if (key == T2) { if (run2 < tie2) mw2 |= 1u << j; run2++; }
        }
    }
    int selTot2; int sb2 = blk_scan_excl(__popc(mw2), selTot2);
    if (tid < SP / 32) {
        int rr = sb2;
        for (int j = 0; j < 32; j++) {
            if ((mw2 >> j) & 1u) g_rpos[bh * MC + (rr++)] = npos[tid * 32 + j];
        }
    }
}

// ---------------- kernel: coalesced gather into token-major bf16 g_xt ----------------
__global__ void __launch_bounds__(256) k_gather(const float* __restrict__ Kin,
                                                const float* __restrict__ Vin) {
    __shared__ int pos[128];
    int bh = blockIdx.y, t0 = blockIdx.x * 128, tid = threadIdx.x;
    if (tid < 128) pos[tid] = g_nonpos[bh * SP + t0 + tid];
    __syncthreads();
    int w = tid >> 5, lane = tid & 31;
    const float4* Kb = (const float4*)(Kin + (size_t)bh * S * D);
    const float4* Vb = (const float4*)(Vin + (size_t)bh * S * D);
    for (int tt = w; tt < 128; tt += 8) {
        int p = pos[tt];
        __nv_bfloat162* X = (__nv_bfloat162*)(g_xt + ((size_t)bh * XR + t0 + 1 + tt) * C0I);
        float4 kk = Kb[(size_t)p * 32 + lane];
        float4 vv = Vb[(size_t)p * 32 + lane];
        X[lane * 2]          = __floats2bfloat162_rn(kk.x, kk.y);
        X[lane * 2 + 1]      = __floats2bfloat162_rn(kk.z, kk.w);
        X[64 + lane * 2]     = __floats2bfloat162_rn(vv.x, vv.y);
        X[64 + lane * 2 + 1] = __floats2bfloat162_rn(vv.z, vv.w);
    }
}

// ---------------- conv as TN bf16 tensor-core GEMM ----------------
// Y[o][t] = silu( sum_{k=(r,ci)} W[o][k] * X[t+r][ci] + bias[o] )
template <int CIN, int COUT, int KTOT, bool TO_H0>
__global__ void __launch_bounds__(256, 2) k_conv(const float* __restrict__ bias) {
    constexpr int LDA = 40;                       // bf16 row stride (80B): LDS conflict-free
    __shared__ bf16 SM[2][2][128 * LDA];          // [buf][A=0/B=1]
    const bf16* Wm = TO_H0 ? g_w0r : g_w1r;
    const bf16* Xs = TO_H0 ? g_xt  : g_h0t;
    int tid = threadIdx.x;
    int n0 = blockIdx.x * 128, m0 = blockIdx.y * 128, bh = blockIdx.z;
    const bf16* Xb = Xs + (size_t)bh * XR * CIN;
    int w = tid >> 5, lane = tid & 31;
    int wm = (w >> 2) * 64, wn = (w & 3) * 32;
    float acc[4][4][4] = {};

    auto LOAD = [&](int kt, int buf) {
        int r = kt / CIN, ci0 = kt % CIN;   // 32-wide chunk never crosses an r boundary
#pragma unroll
        for (int q = 0; q < 2; q++) {
            int e = tid + q * 256; int m = e >> 2, kp = (e & 3) * 8;
            CP16(&SM[buf][0][m * LDA + kp], Wm + (size_t)(m0 + m) * KTOT + kt + kp);
        }
#pragma unroll
        for (int q = 0; q < 2; q++) {
            int e = tid + q * 256; int n = e >> 2, kp = (e & 3) * 8;
            CP16(&SM[buf][1][n * LDA + kp], Xb + (size_t)(n0 + n + r) * CIN + ci0 + kp);
        }
    };
    auto COMP = [&](int buf) {
#pragma unroll
        for (int ks = 0; ks < 32; ks += 16) {
            unsigned a[4][4], b[4][2];
#pragma unroll
            for (int mi = 0; mi < 4; mi++) {
                int row = wm + mi * 16 + (lane & 15);
                int col = ks + ((lane >> 4) << 3);
                ldsm4(a[mi], &SM[buf][0][row * LDA + col]);
            }
#pragma unroll
            for (int ni = 0; ni < 4; ni++) {
                int row = wn + ni * 8 + (lane & 7);
                int col = ks + (((lane >> 3) & 1) << 3);
                ldsm2(b[ni], &SM[buf][1][row * LDA + col]);
            }
#pragma unroll
            for (int mi = 0; mi < 4; mi++)
#pragma unroll
                for (int ni = 0; ni < 4; ni++) mma16(acc[mi][ni], a[mi], b[ni]);
        }
    };

    LOAD(0, 0);
    asm volatile("cp.async.commit_group;");
    int buf = 0;
    for (int kt = 0; kt < KTOT; kt += 32) {
        if (kt + 32 < KTOT) {
            LOAD(kt + 32, buf ^ 1);
            asm volatile("cp.async.commit_group;");
            asm volatile("cp.async.wait_group 1;");
        } else {
            asm volatile("cp.async.wait_group 0;");
        }
        __syncthreads();
        COMP(buf);
        __syncthreads();
        buf ^= 1;
    }

    if (TO_H0) {
        // stage C (token-major) through smem for coalesced bf16 stores
        constexpr int LDC = 136;                  // 272B rows: 16B-aligned, conflict-spread
        bf16* Cs = &SM[0][0][0];                  // 128*136 bf16 = 34816B <= 40960B
#pragma unroll
        for (int mi = 0; mi < 4; mi++)
#pragma unroll
            for (int ni = 0; ni < 4; ni++)
#pragma unroll
                for (int rg = 0; rg < 4; rg++) {
                    int ml = wm + mi * 16 + (lane >> 2) + ((rg >> 1) ? 8 : 0);
                    int nl = wn + ni * 8 + (lane & 3) * 2 + (rg & 1);
                    float v = acc[mi][ni][rg] + bias[m0 + ml];
                    v = v / (1.f + __expf(-v));
                    Cs[nl * LDC + ml] = __float2bfloat16(v);
                }
        __syncthreads();
        bf16* Yb = g_h0t + ((size_t)bh * XR + n0 + 1) * COUT + m0;
        for (int e = tid; e < 128 * 16; e += 256) {
            int t = e >> 4, ch = e & 15;
            *(uint4*)(Yb + (size_t)t * COUT + ch * 8) = *(const uint4*)(Cs + t * LDC + ch * 8);
        }
    } else {
        float* Yb = g_p + (size_t)bh * (size_t)COUT * SP;
#pragma unroll
        for (int mi = 0; mi < 4; mi++)
#pragma unroll
            for (int ni = 0; ni < 4; ni++)
#pragma unroll
                for (int half = 0; half < 2; half++) {
                    int ml = wm + mi * 16 + (lane >> 2) + half * 8;
                    int t  = n0 + wn + ni * 8 + (lane & 3) * 2;
                    float v0 = acc[mi][ni][half * 2 + 0] + bias[m0 + ml];
                    float v1 = acc[mi][ni][half * 2 + 1] + bias[m0 + ml];
                    v0 = v0 / (1.f + __expf(-v0));
                    v1 = v1 / (1.f + __expf(-v1));
                    *(float2*)(Yb + (size_t)(m0 + ml) * SP + t) = make_float2(v0, v1);
                }
    }
}

// ---------------- row softmax over SP: fp32 in, bf16 out ----------------
__device__ float blk_max256(float v) {
    __shared__ float sh[8]; __shared__ float res;
    int tid = threadIdx.x;
    __syncthreads();
#pragma unroll
    for (int o = 16; o; o >>= 1) v = fmaxf(v, __shfl_xor_sync(0xffffffffu, v, o));
    if ((tid & 31) == 0) sh[tid >> 5] = v;
    __syncthreads();
    if (tid == 0) { float m = sh[0]; for (int i = 1; i < 8; i++) m = fmaxf(m, sh[i]); res = m; }
    __syncthreads();
    return res;
}
__device__ float blk_sum256(float v) {
    __shared__ float sh[8]; __shared__ float res;
    int tid = threadIdx.x;
    __syncthreads();
#pragma unroll
    for (int o = 16; o; o >>= 1) v += __shfl_xor_sync(0xffffffffu, v, o);
    if ((tid & 31) == 0) sh[tid >> 5] = v;
    __syncthreads();
    if (tid == 0) { float s = 0; for (int i = 0; i < 8; i++) s += sh[i]; res = s; }
    __syncthreads();
    return res;
}
__global__ void __launch_bounds__(256) k_softmax() {
    int bh = blockIdx.y, m = blockIdx.x, tid = threadIdx.x;
    const float* row = g_p + ((size_t)bh * MC + m) * SP;
    bf16* rowb = g_pb + ((size_t)bh * MC + m) * SP;
    float v[31]; float mx = -1e30f;
#pragma unroll
    for (int q = 0; q < 31; q++) { v[q] = row[tid + q * 256]; mx = fmaxf(mx, v[q]); }
    mx = blk_max256(mx);
    float s = 0.f;
#pragma unroll
    for (int q = 0; q < 31; q++) { float e = __expf(v[q] - mx); v[q] = e; s += e; }
    s = blk_sum256(s);
    float inv = 1.f / s;
#pragma unroll
    for (int q = 0; q < 31; q++) rowb[tid + q * 256] = __float2bfloat16(v[q] * inv);
}

// ---------------- merge: bf16 TN GEMM (256x256xSP) per bh + exact fp32 residual ----------------
__global__ void __launch_bounds__(256, 2) k_merge(const float* __restrict__ Kin,
                                                  const float* __restrict__ Vin,
                                                  const float* __restrict__ nrmp,
                                                  float* __restrict__ out) {
    constexpr int LDA = 40;
    constexpr int LDB = 136;
    __shared__ bf16 SA[2][128 * LDA];
    __shared__ bf16 SB[2][32 * LDB];
    int tid = threadIdx.x;
    int n0 = blockIdx.x * 128, m0 = blockIdx.y * 128, bh = blockIdx.z;
    const bf16* A  = g_pb + (size_t)bh * MC * SP;
    const bf16* Xb = g_xt + (size_t)bh * XR * C0I;
    int w = tid >> 5, lane = tid & 31;
    int wm = (w >> 2) * 64, wn = (w & 3) * 32;
    float acc[4][4][4] = {};

    auto LOAD = [&](int kt, int buf) {
#pragma unroll
        for (int q = 0; q < 2; q++) {
            int e = tid + q * 256; int m = e >> 2, kp = (e & 3) * 8;
            CP16(&SA[buf][m * LDA + kp], A + (size_t)(m0 + m) * SP + kt + kp);
        }
#pragma unroll
        for (int q = 0; q < 2; q++) {
            int e = tid + q * 256; int k = e >> 4, ch = e & 15;
            CP16(&SB[buf][k * LDB + ch * 8], Xb + (size_t)(kt + k + 1) * C0I + n0 + ch * 8);
        }
    };
    auto COMP = [&](int buf) {
#pragma unroll
        for (int ks = 0; ks < 32; ks += 16) {
            unsigned a[4][4], b[4][2];
#pragma unroll
            for (int mi = 0; mi < 4; mi++) {
                int row = wm + mi * 16 + (lane & 15);
                int col = ks + ((lane >> 4) << 3);
                ldsm4(a[mi], &SA[buf][row * LDA + col]);
            }
#pragma unroll
            for (int ni = 0; ni < 4; ni++) {
                int row = ks + (lane & 15);
                ldsm2t(b[ni], &SB[buf][row * LDB + wn + ni * 8]);
            }
#pragma unroll
            for (int mi = 0; mi < 4; mi++)
#pragma unroll
                for (int ni = 0; ni < 4; ni++) mma16(acc[mi][ni], a[mi], b[ni]);
        }
    };

    LOAD(0, 0);
    asm volatile("cp.async.commit_group;");
    int buf = 0;
    for (int kt = 0; kt < SP; kt += 32) {
        if (kt + 32 < SP) {
            LOAD(kt + 32, buf ^ 1);
            asm volatile("cp.async.commit_group;");
            asm volatile("cp.async.wait_group 1;");
        } else {
            asm volatile("cp.async.wait_group 0;");
        }
        __syncthreads();
        COMP(buf);
        __syncthreads();
        buf ^= 1;
    }

    float nrm = nrmp[0], rn = 1.f - nrm;
#pragma unroll
    for (int mi = 0; mi < 4; mi++)
#pragma unroll
        for (int ni = 0; ni < 4; ni++)
#pragma unroll
            for (int rg = 0; rg < 4; rg++) {
                int ml = wm + mi * 16 + (lane >> 2) + ((rg >> 1) ? 8 : 0);
                int nl = wn + ni * 8 + (lane & 3) * 2 + (rg & 1);
                int m = m0 + ml, n = n0 + nl;
                int rp = g_rpos[bh * MC + m];
                float res; float* dst;
                if (n < 128) {
                    res = Kin[((size_t)bh * S + rp) * D + n];
                    dst = out + ((size_t)bh * 512 + 256 + m) * 128 + n;
                } else {
                    res = Vin[((size_t)bh * S + rp) * D + n - 128];
                    dst = out + VOFF + ((size_t)bh * 512 + 256 + m) * 128 + n - 128;
                }
                *dst = nrm * acc[mi][ni][rg] + rn * res;
            }
}

// ---------------- exact hh gather into output rows [0,256) ----------------
__global__ void __launch_bounds__(256) k_hhcopy(const float* __restrict__ Kin,
                                                const float* __restrict__ Vin,
                                                float* __restrict__ out) {
    int bh = blockIdx.x, tid = threadIdx.x;
    const float* Kb = Kin + (size_t)bh * S * D;
    const float* Vb = Vin + (size_t)bh * S * D;
    float* ok = out + (size_t)bh * 512 * 128;
    float* ov = out + VOFF + (size_t)bh * 512 * 128;
    for (int e = tid; e < KEEP * D; e += 256) {
        int j = e >> 7, d = e & 127;
        int pos = g_hhpos[bh * KEEP + j];
        ok[(size_t)j * 128 + d] = Kb[(size_t)pos * D + d];
        ov[(size_t)j * 128 + d] = Vb[(size_t)pos * D + d];
    }
}

// ---------------- launch ----------------
extern "C" void kernel_launch(void* const* d_in, const int* in_sizes, int n_in,
                              void* d_out, int out_size) {
    const float* Kin = (const float*)d_in[0];
    const float* Vin = (const float*)d_in[1];
    const float* sc  = (const float*)d_in[2];
    const float* w0  = (const float*)d_in[3];
    const float* b0  = (const float*)d_in[4];
    const float* w1  = (const float*)d_in[5];
    const float* b1  = (const float*)d_in[6];
    const float* nrm = (const float*)d_in[7];
    float* out = (float*)d_out;
    (void)in_sizes; (void)n_in; (void)out_size;

    k_wprep<<<768, 256>>>(w0, w1);
    k_zeropad<<<128, 256>>>();
    k_select<<<BH, 256>>>(sc);
    {
        dim3 g(SP / 128, BH);
        k_gather<<<g, 256>>>(Kin, Vin);
    }
    {
        dim3 g0(SP / 128, C0O / 128, BH);          // 62 x 4 x 64
        k_conv<C0I, C0O, K0, true><<<g0, 256>>>(b0);
        dim3 g1(SP / 128, C1O / 128, BH);          // 62 x 2 x 64
        k_conv<C1I, C1O, K1, false><<<g1, 256>>>(b1);
    }
    {
        dim3 gs(MC, BH);
        k_softmax<<<gs, 256>>>();
    }
    {
        dim3 gm(2, 2, BH);
        k_merge<<<gm, 256>>>(Kin, Vin, nrm, out);
    }
    k_hhcopy<<<BH, 256>>>(Kin, Vin, out);
}

// round 11
// speedup vs baseline: 6.9685x; 1.0050x over previous
#include <cuda_runtime.h>
#include <cuda_bf16.h>
#include <math.h>

using bf16 = __nv_bfloat16;

// ---------------- problem constants ----------------
constexpr int BH   = 64;      // b*h = 2*32
constexpr int S    = 8192;
constexpr int D    = 128;
constexpr int SEARCH = S - 64;        // 8128
constexpr int KTOP = 192;             // KEEP_HH - LOCAL_LEN
constexpr int KEEP = 256;             // KEEP_HH
constexpr int SP   = S - KEEP;        // 7936
constexpr int MC   = 256;             // MEM_COMPRESS
constexpr int C0I  = 256, C0O = 512, K0 = 768;
constexpr int C1I  = 512, C1O = 256, K1 = 1536;
constexpr int XR   = SP + 2;          // token rows incl. zero pads at 0 and SP+1
constexpr size_t VOFF = (size_t)BH * 512 * 128;   // values offset in d_out

// ---------------- device scratch ----------------
__device__ int  g_hhpos[BH * KEEP];
__device__ int  g_nonpos[BH * SP];
__device__ int  g_rpos[BH * MC];
__device__ __align__(256) bf16 g_xt [(size_t)BH * XR * C0I];   // gathered [k|v] token-major bf16
__device__ __align__(256) bf16 g_h0t[(size_t)BH * XR * C1I];   // conv0 out (silu) token-major bf16
__device__ __align__(256) bf16 g_pb [(size_t)BH * MC * SP];    // conv1 silu logits -> probs (in place)
__device__ __align__(256) bf16 g_w0r[C0O * K0];                // weights bf16, k = r*CIN + ci
__device__ __align__(256) bf16 g_w1r[C1O * K1];

// ---------------- low-level helpers ----------------
#define CP16(dst, src) asm volatile("cp.async.ca.shared.global [%0], [%1], 16;\n" \
    :: "r"((unsigned)__cvta_generic_to_shared(dst)), "l"(src))

__device__ __forceinline__ void ldsm4(unsigned* a, const void* p) {
    unsigned addr = (unsigned)__cvta_generic_to_shared(p);
    asm volatile("ldmatrix.sync.aligned.m8n8.x4.shared.b16 {%0,%1,%2,%3}, [%4];"
                 : "=r"(a[0]), "=r"(a[1]), "=r"(a[2]), "=r"(a[3]) : "r"(addr));
}
__device__ __forceinline__ void ldsm2(unsigned* b, const void* p) {
    unsigned addr = (unsigned)__cvta_generic_to_shared(p);
    asm volatile("ldmatrix.sync.aligned.m8n8.x2.shared.b16 {%0,%1}, [%2];"
                 : "=r"(b[0]), "=r"(b[1]) : "r"(addr));
}
__device__ __forceinline__ void ldsm2t(unsigned* b, const void* p) {
    unsigned addr = (unsigned)__cvta_generic_to_shared(p);
    asm volatile("ldmatrix.sync.aligned.m8n8.x2.trans.shared.b16 {%0,%1}, [%2];"
                 : "=r"(b[0]), "=r"(b[1]) : "r"(addr));
}
__device__ __forceinline__ void mma16(float* c, const unsigned* a, const unsigned* b) {
    asm volatile(
        "mma.sync.aligned.m16n8k16.row.col.f32.bf16.bf16.f32 "
        "{%0,%1,%2,%3},{%4,%5,%6,%7},{%8,%9},{%0,%1,%2,%3};\n"
        : "+f"(c[0]), "+f"(c[1]), "+f"(c[2]), "+f"(c[3])
        : "r"(a[0]), "r"(a[1]), "r"(a[2]), "r"(a[3]), "r"(b[0]), "r"(b[1]));
}

__device__ __forceinline__ unsigned f2key(float f) {
    unsigned u = __float_as_uint(f);
    return (u & 0x80000000u) ? ~u : (u | 0x80000000u);
}

__device__ int blk_scan_excl(int v, int& total) {
    __shared__ int wsum[8];
    __shared__ int tot;
    int tid = threadIdx.x, lane = tid & 31, w = tid >> 5;
    __syncthreads();
    int incl = v;
#pragma unroll
    for (int o = 1; o < 32; o <<= 1) {
        int y = __shfl_up_sync(0xffffffffu, incl, o);
        if (lane >= o) incl += y;
    }
    if (lane == 31) wsum[w] = incl;
    __syncthreads();
    if (tid == 0) {
        int run = 0;
#pragma unroll
        for (int i = 0; i < 8; i++) { int t = wsum[i]; wsum[i] = run; run += t; }
        tot = run;
    }
    __syncthreads();
    total = tot;
    return wsum[w] + incl - v;
}

__device__ void radix_topk(const float* __restrict__ sc, const int* __restrict__ idxmap,
                           int n, int k, unsigned& T, int& tieNeed) {
    __shared__ unsigned hist[256];
    __shared__ unsigned sh_pref;
    __shared__ int      sh_need;
    int tid = threadIdx.x;
    unsigned pref = 0; int need = k;
    for (int shift = 24; shift >= 0; shift -= 8) {
        __syncthreads();
        hist[tid] = 0;
        __syncthreads();
        for (int i = tid; i < n; i += 256) {
            int idx = idxmap ? idxmap[i] : i;
            unsigned key = f2key(sc[idx]);
            unsigned long long hi = (unsigned long long)key  >> (shift + 8);
            unsigned long long ph = (unsigned long long)pref >> (shift + 8);
            if (hi == ph) atomicAdd(&hist[(key >> shift) & 255], 1u);
        }
        __syncthreads();
        if (tid == 0) {
            unsigned cum = 0; int b = 255;
            for (; b > 0; b--) { unsigned h = hist[b]; if (cum + h >= (unsigned)need) break; cum += h; }
            sh_pref = pref | ((unsigned)b << shift);
            sh_need = need - (int)cum;
        }
        __syncthreads();
        pref = sh_pref; need = sh_need;
    }
    T = pref; tieNeed = need;
}

// ---------------- kernel: weight reorder (k = r*CIN + ci), to bf16 ----------------
__global__ void k_wprep(const float* __restrict__ w0, const float* __restrict__ w1) {
    int n0 = C0O * K0, n1 = C1O * K1;
    for (int e = blockIdx.x * blockDim.x + threadIdx.x; e < n0 + n1; e += gridDim.x * blockDim.x) {
        if (e < n0) {
            int o = e / K0, k = e % K0, r = k / C0I, i = k % C0I;
            g_w0r[e] = __float2bfloat16(w0[(o * C0I + i) * 3 + r]);
        } else {
            int e2 = e - n0;
            int o = e2 / K1, k = e2 % K1, r = k / C1I, i = k % C1I;
            g_w1r[e2] = __float2bfloat16(w1[(o * C1I + i) * 3 + r]);
        }
    }
}

// ---------------- kernel: zero conv pad rows ----------------
__global__ void k_zeropad() {
    int stride = gridDim.x * blockDim.x;
    int tid = blockIdx.x * blockDim.x + threadIdx.x;
    bf16 z = __float2bfloat16(0.f);
    for (int e = tid; e < BH * C0I; e += stride) {
        int bh = e / C0I, c = e % C0I;
        g_xt[((size_t)bh * XR + 0) * C0I + c] = z;
        g_xt[((size_t)bh * XR + SP + 1) * C0I + c] = z;
    }
    for (int e = tid; e < BH * C1I; e += stride) {
        int bh = e / C1I, c = e % C1I;
        g_h0t[((size_t)bh * XR + 0) * C1I + c] = z;
        g_h0t[((size_t)bh * XR + SP + 1) * C1I + c] = z;
    }
}

// ---------------- kernel: exact selection (both top-k's) ----------------
__global__ void __launch_bounds__(256) k_select(const float* __restrict__ scores) {
    int bh = blockIdx.x, tid = threadIdx.x;
    const float* sc = scores + (size_t)bh * S;

    unsigned T; int tieNeed;
    radix_topk(sc, nullptr, SEARCH, KTOP, T, tieNeed);

    int base = tid * 32;
    int eqc = 0;
    for (int j = 0; j < 32; j++) {
        int i = base + j;
        if (i < SEARCH && f2key(sc[i]) == T) eqc++;
    }
    int eqTot; int eqBase = blk_scan_excl(eqc, eqTot);
    unsigned mw = 0;
    {
        int run = eqBase;
        for (int j = 0; j < 32; j++) {
            int i = base + j;
            if (i >= SEARCH) { mw |= 1u << j; }
            else {
                unsigned key = f2key(sc[i]);
                if (key > T) mw |= 1u << j;
                else if (key == T) { if (run < tieNeed) mw |= 1u << j; run++; }
            }
        }
    }
    int selTot; int selBase = blk_scan_excl(__popc(mw), selTot);
    {
        int sr = selBase, nr = base - selBase;
        for (int j = 0; j < 32; j++) {
            int i = base + j;
            if ((mw >> j) & 1u) g_hhpos[bh * KEEP + (sr++)] = i;
            else                g_nonpos[bh * SP   + (nr++)] = i;
        }
    }
    __syncthreads();

    const int* npos = g_nonpos + bh * SP;
    unsigned T2; int tie2;
    radix_topk(sc, npos, SP, MC, T2, tie2);

    int eqc2 = 0;
    if (tid < SP / 32) {
        for (int j = 0; j < 32; j++) {
            int s = tid * 32 + j;
            if (f2key(sc[npos[s]]) == T2) eqc2++;
        }
    }
    int eqTot2; int eqB2 = blk_scan_excl(eqc2, eqTot2);
    unsigned mw2 = 0;
    if (tid < SP / 32) {
        int run2 = eqB2;
        for (int j = 0; j < 32; j++) {
            int s = tid * 32 + j;
            unsigned key = f2key(sc[npos[s]]);
            if (key > T2) mw2 |= 1u << j;
            else if (key == T2) { if (run2 < tie2) mw2 |= 1u << j; run2++; }
        }
    }
    int selTot2; int sb2 = blk_scan_excl(__popc(mw2), selTot2);
    if (tid < SP / 32) {
        int rr = sb2;
        for (int j = 0; j < 32; j++) {
            if ((mw2 >> j) & 1u) g_rpos[bh * MC + (rr++)] = npos[tid * 32 + j];
        }
    }
}

// ---------------- kernel: coalesced gather into token-major bf16 g_xt ----------------
__global__ void __launch_bounds__(256) k_gather(const float* __restrict__ Kin,
                                                const float* __restrict__ Vin) {
    __shared__ int pos[128];
    int bh = blockIdx.y, t0 = blockIdx.x * 128, tid = threadIdx.x;
    if (tid < 128) pos[tid] = g_nonpos[bh * SP + t0 + tid];
    __syncthreads();
    int w = tid >> 5, lane = tid & 31;
    const float4* Kb = (const float4*)(Kin + (size_t)bh * S * D);
    const float4* Vb = (const float4*)(Vin + (size_t)bh * S * D);
    for (int tt = w; tt < 128; tt += 8) {
        int p = pos[tt];
        __nv_bfloat162* X = (__nv_bfloat162*)(g_xt + ((size_t)bh * XR + t0 + 1 + tt) * C0I);
        float4 kk = Kb[(size_t)p * 32 + lane];
        float4 vv = Vb[(size_t)p * 32 + lane];
        X[lane * 2]          = __floats2bfloat162_rn(kk.x, kk.y);
        X[lane * 2 + 1]      = __floats2bfloat162_rn(kk.z, kk.w);
        X[64 + lane * 2]     = __floats2bfloat162_rn(vv.x, vv.y);
        X[64 + lane * 2 + 1] = __floats2bfloat162_rn(vv.z, vv.w);
    }
}

// ---------------- conv as TN bf16 tensor-core GEMM (round-7 proven structure) ----------------
// Y[o][t] = silu( sum_{k=(r,ci)} W[o][k] * X[t+r][ci] + bias[o] )
template <int CIN, int COUT, int KTOT, bool TO_H0>
__global__ void __launch_bounds__(256, 2) k_conv(const float* __restrict__ bias) {
    constexpr int LDA = 40;                       // bf16 row stride (80B): LDS conflict-free
    __shared__ bf16 SM[2][2][128 * LDA];          // [buf][A=0/B=1]
    const bf16* Wm = TO_H0 ? g_w0r : g_w1r;
    const bf16* Xs = TO_H0 ? g_xt  : g_h0t;
    int tid = threadIdx.x;
    int n0 = blockIdx.x * 128, m0 = blockIdx.y * 128, bh = blockIdx.z;
    const bf16* Xb = Xs + (size_t)bh * XR * CIN;
    int w = tid >> 5, lane = tid & 31;
    int wm = (w >> 2) * 64, wn = (w & 3) * 32;
    float acc[4][4][4] = {};

    auto LOAD = [&](int kt, int buf) {
        int r = kt / CIN, ci0 = kt % CIN;   // 32-wide chunk never crosses an r boundary
#pragma unroll
        for (int q = 0; q < 2; q++) {
            int e = tid + q * 256; int m = e >> 2, kp = (e & 3) * 8;
            CP16(&SM[buf][0][m * LDA + kp], Wm + (size_t)(m0 + m) * KTOT + kt + kp);
        }
#pragma unroll
        for (int q = 0; q < 2; q++) {
            int e = tid + q * 256; int n = e >> 2, kp = (e & 3) * 8;
            CP16(&SM[buf][1][n * LDA + kp], Xb + (size_t)(n0 + n + r) * CIN + ci0 + kp);
        }
    };
    auto COMP = [&](int buf) {
#pragma unroll
        for (int ks = 0; ks < 32; ks += 16) {
            unsigned a[4][4], b[4][2];
#pragma unroll
            for (int mi = 0; mi < 4; mi++) {
                int row = wm + mi * 16 + (lane & 15);
                int col = ks + ((lane >> 4) << 3);
                ldsm4(a[mi], &SM[buf][0][row * LDA + col]);
            }
#pragma unroll
            for (int ni = 0; ni < 4; ni++) {
                int row = wn + ni * 8 + (lane & 7);
                int col = ks + (((lane >> 3) & 1) << 3);
                ldsm2(b[ni], &SM[buf][1][row * LDA + col]);
            }
#pragma unroll
            for (int mi = 0; mi < 4; mi++)
#pragma unroll
                for (int ni = 0; ni < 4; ni++) mma16(acc[mi][ni], a[mi], b[ni]);
        }
    };

    LOAD(0, 0);
    asm volatile("cp.async.commit_group;");
    int buf = 0;
    for (int kt = 0; kt < KTOT; kt += 32) {
        if (kt + 32 < KTOT) {
            LOAD(kt + 32, buf ^ 1);
            asm volatile("cp.async.commit_group;");
            asm volatile("cp.async.wait_group 1;");
        } else {
            asm volatile("cp.async.wait_group 0;");
        }
        __syncthreads();
        COMP(buf);
        __syncthreads();
        buf ^= 1;
    }

    if (TO_H0) {
        // stage C (token-major) through smem for coalesced bf16 stores
        constexpr int LDC = 136;                  // 272B rows: 16B-aligned, conflict-spread
        bf16* Cs = &SM[0][0][0];                  // 128*136 bf16 = 34816B <= 40960B
#pragma unroll
        for (int mi = 0; mi < 4; mi++)
#pragma unroll
            for (int ni = 0; ni < 4; ni++)
#pragma unroll
                for (int rg = 0; rg < 4; rg++) {
                    int ml = wm + mi * 16 + (lane >> 2) + ((rg >> 1) ? 8 : 0);
                    int nl = wn + ni * 8 + (lane & 3) * 2 + (rg & 1);
                    float v = acc[mi][ni][rg] + bias[m0 + ml];
                    v = v / (1.f + __expf(-v));
                    Cs[nl * LDC + ml] = __float2bfloat16(v);
                }
        __syncthreads();
        bf16* Yb = g_h0t + ((size_t)bh * XR + n0 + 1) * COUT + m0;
        for (int e = tid; e < 128 * 16; e += 256) {
            int t = e >> 4, ch = e & 15;
            *(uint4*)(Yb + (size_t)t * COUT + ch * 8) = *(const uint4*)(Cs + t * LDC + ch * 8);
        }
    } else {
        // direct bf16x2 stores of silu'd logits into g_pb [m][t]
        bf16* Yb = g_pb + (size_t)bh * (size_t)COUT * SP;
#pragma unroll
        for (int mi = 0; mi < 4; mi++)
#pragma unroll
            for (int ni = 0; ni < 4; ni++)
#pragma unroll
                for (int half = 0; half < 2; half++) {
                    int ml = wm + mi * 16 + (lane >> 2) + half * 8;
                    int t  = n0 + wn + ni * 8 + (lane & 3) * 2;
                    float v0 = acc[mi][ni][half * 2 + 0] + bias[m0 + ml];
                    float v1 = acc[mi][ni][half * 2 + 1] + bias[m0 + ml];
                    v0 = v0 / (1.f + __expf(-v0));
                    v1 = v1 / (1.f + __expf(-v1));
                    *(__nv_bfloat162*)(Yb + (size_t)(m0 + ml) * SP + t) =
                        __floats2bfloat162_rn(v0, v1);
                }
    }
}

// ---------------- row softmax in place on bf16 logits ----------------
__device__ float blk_max256(float v) {
    __shared__ float sh[8]; __shared__ float res;
    int tid = threadIdx.x;
    __syncthreads();
#pragma unroll
    for (int o = 16; o; o >>= 1) v = fmaxf(v, __shfl_xor_sync(0xffffffffu, v, o));
    if ((tid & 31) == 0) sh[tid >> 5] = v;
    __syncthreads();
    if (tid == 0) { float m = sh[0]; for (int i = 1; i < 8; i++) m = fmaxf(m, sh[i]); res = m; }
    __syncthreads();
    return res;
}
__device__ float blk_sum256(float v) {
    __shared__ float sh[8]; __shared__ float res;
    int tid = threadIdx.x;
    __syncthreads();
#pragma unroll
    for (int o = 16; o; o >>= 1) v += __shfl_xor_sync(0xffffffffu, v, o);
    if ((tid & 31) == 0) sh[tid >> 5] = v;
    __syncthreads();
    if (tid == 0) { float s = 0; for (int i = 0; i < 8; i++) s += sh[i]; res = s; }
    __syncthreads();
    return res;
}
__global__ void __launch_bounds__(256) k_softmax() {
    int bh = blockIdx.y, m = blockIdx.x, tid = threadIdx.x;
    bf16* row = g_pb + ((size_t)bh * MC + m) * SP;
    float v[31]; float mx = -1e30f;
#pragma unroll
    for (int q = 0; q < 31; q++) { v[q] = __bfloat162float(row[tid + q * 256]); mx = fmaxf(mx, v[q]); }
    mx = blk_max256(mx);
    float s = 0.f;
#pragma unroll
    for (int q = 0; q < 31; q++) { float e = __expf(v[q] - mx); v[q] = e; s += e; }
    s = blk_sum256(s);
    float inv = 1.f / s;
#pragma unroll
    for (int q = 0; q < 31; q++) row[tid + q * 256] = __float2bfloat16(v[q] * inv);
}

// ---------------- merge: bf16 TN GEMM + exact fp32 residual (round-7 structure) ----------------
__global__ void __launch_bounds__(256, 2) k_merge(const float* __restrict__ Kin,
                                                  const float* __restrict__ Vin,
                                                  const float* __restrict__ nrmp,
                                                  float* __restrict__ out) {
    constexpr int LDA = 40;
    constexpr int LDB = 136;
    __shared__ bf16 SA[2][128 * LDA];
    __shared__ bf16 SB[2][32 * LDB];
    int tid = threadIdx.x;
    int n0 = blockIdx.x * 128, m0 = blockIdx.y * 128, bh = blockIdx.z;
    const bf16* A  = g_pb + (size_t)bh * MC * SP;
    const bf16* Xb = g_xt + (size_t)bh * XR * C0I;
    int w = tid >> 5, lane = tid & 31;
    int wm = (w >> 2) * 64, wn = (w & 3) * 32;
    float acc[4][4][4] = {};

    auto LOAD = [&](int kt, int buf) {
#pragma unroll
        for (int q = 0; q < 2; q++) {
            int e = tid + q * 256; int m = e >> 2, kp = (e & 3) * 8;
            CP16(&SA[buf][m * LDA + kp], A + (size_t)(m0 + m) * SP + kt + kp);
        }
#pragma unroll
        for (int q = 0; q < 2; q++) {
            int e = tid + q * 256; int k = e >> 4, ch = e & 15;
            CP16(&SB[buf][k * LDB + ch * 8], Xb + (size_t)(kt + k + 1) * C0I + n0 + ch * 8);
        }
    };
    auto COMP = [&](int buf) {
#pragma unroll
        for (int ks = 0; ks < 32; ks += 16) {
            unsigned a[4][4], b[4][2];
#pragma unroll
            for (int mi = 0; mi < 4; mi++) {
                int row = wm + mi * 16 + (lane & 15);
                int col = ks + ((lane >> 4) << 3);
                ldsm4(a[mi], &SA[buf][row * LDA + col]);
            }
#pragma unroll
            for (int ni = 0; ni < 4; ni++) {
                int row = ks + (lane & 15);
                ldsm2t(b[ni], &SB[buf][row * LDB + wn + ni * 8]);
            }
#pragma unroll
            for (int mi = 0; mi < 4; mi++)
#pragma unroll
                for (int ni = 0; ni < 4; ni++) mma16(acc[mi][ni], a[mi], b[ni]);
        }
    };

    LOAD(0, 0);
    asm volatile("cp.async.commit_group;");
    int buf = 0;
    for (int kt = 0; kt < SP; kt += 32) {
        if (kt + 32 < SP) {
            LOAD(kt + 32, buf ^ 1);
            asm volatile("cp.async.commit_group;");
            asm volatile("cp.async.wait_group 1;");
        } else {
            asm volatile("cp.async.wait_group 0;");
        }
        __syncthreads();
        COMP(buf);
        __syncthreads();
        buf ^= 1;
    }

    float nrm = nrmp[0], rn = 1.f - nrm;
#pragma unroll
    for (int mi = 0; mi < 4; mi++)
#pragma unroll
        for (int ni = 0; ni < 4; ni++)
#pragma unroll
            for (int rg = 0; rg < 4; rg++) {
                int ml = wm + mi * 16 + (lane >> 2) + ((rg >> 1) ? 8 : 0);
                int nl = wn + ni * 8 + (lane & 3) * 2 + (rg & 1);
                int m = m0 + ml, n = n0 + nl;
                int rp = g_rpos[bh * MC + m];
                float res; float* dst;
                if (n < 128) {
                    res = Kin[((size_t)bh * S + rp) * D + n];
                    dst = out + ((size_t)bh * 512 + 256 + m) * 128 + n;
                } else {
                    res = Vin[((size_t)bh * S + rp) * D + n - 128];
                    dst = out + VOFF + ((size_t)bh * 512 + 256 + m) * 128 + n - 128;
                }
                *dst = nrm * acc[mi][ni][rg] + rn * res;
            }
}

// ---------------- exact hh gather into output rows [0,256) ----------------
__global__ void __launch_bounds__(256) k_hhcopy(const float* __restrict__ Kin,
                                                const float* __restrict__ Vin,
                                                float* __restrict__ out) {
    int bh = blockIdx.x, tid = threadIdx.x;
    const float* Kb = Kin + (size_t)bh * S * D;
    const float* Vb = Vin + (size_t)bh * S * D;
    float* ok = out + (size_t)bh * 512 * 128;
    float* ov = out + VOFF + (size_t)bh * 512 * 128;
    for (int e = tid; e < KEEP * D; e += 256) {
        int j = e >> 7, d = e & 127;
        int pos = g_hhpos[bh * KEEP + j];
        ok[(size_t)j * 128 + d] = Kb[(size_t)pos * D + d];
        ov[(size_t)j * 128 + d] = Vb[(size_t)pos * D + d];
    }
}

// ---------------- launch ----------------
extern "C" void kernel_launch(void* const* d_in, const int* in_sizes, int n_in,
                              void* d_out, int out_size) {
    const float* Kin = (const float*)d_in[0];
    const float* Vin = (const float*)d_in[1];
    const float* sc  = (const float*)d_in[2];
    const float* w0  = (const float*)d_in[3];
    const float* b0  = (const float*)d_in[4];
    const float* w1  = (const float*)d_in[5];
    const float* b1  = (const float*)d_in[6];
    const float* nrm = (const float*)d_in[7];
    float* out = (float*)d_out;
    (void)in_sizes; (void)n_in; (void)out_size;

    k_wprep<<<768, 256>>>(w0, w1);
    k_zeropad<<<128, 256>>>();
    k_select<<<BH, 256>>>(sc);
    {
        dim3 g(SP / 128, BH);
        k_gather<<<g, 256>>>(Kin, Vin);
    }
    {
        dim3 g0(SP / 128, C0O / 128, BH);          // 62 x 4 x 64
        k_conv<C0I, C0O, K0, true><<<g0, 256>>>(b0);
        dim3 g1(SP / 128, C1O / 128, BH);          // 62 x 2 x 64
        k_conv<C1I, C1O, K1, false><<<g1, 256>>>(b1);
    }
    {
        dim3 gs(MC, BH);
        k_softmax<<<gs, 256>>>();
    }
    {
        dim3 gm(2, 2, BH);
        k_merge<<<gm, 256>>>(Kin, Vin, nrm, out);
    }
    k_hhcopy<<<BH, 256>>>(Kin, Vin, out);
}

// round 14
// speedup vs baseline: 7.0469x; 1.0113x over previous
#include <cuda_runtime.h>
#include <cuda_bf16.h>
#include <math.h>

using bf16 = __nv_bfloat16;

// ---------------- problem constants ----------------
constexpr int BH   = 64;      // b*h = 2*32
constexpr int S    = 8192;
constexpr int D    = 128;
constexpr int SEARCH = S - 64;        // 8128
constexpr int KTOP = 192;             // KEEP_HH - LOCAL_LEN
constexpr int KEEP = 256;             // KEEP_HH
constexpr int SP   = S - KEEP;        // 7936
constexpr int MC   = 256;             // MEM_COMPRESS
constexpr int C0I  = 256, C0O = 512, K0 = 768;
constexpr int C1I  = 512, C1O = 256, K1 = 1536;
constexpr int XR   = SP + 2;          // token rows incl. zero pads at 0 and SP+1
constexpr size_t VOFF = (size_t)BH * 512 * 128;   // values offset in d_out

// ---------------- device scratch ----------------
__device__ int  g_hhpos[BH * KEEP];
__device__ int  g_nonpos[BH * SP];
__device__ int  g_rpos[BH * MC];
__device__ __align__(256) bf16 g_xt [(size_t)BH * XR * C0I];   // gathered [k|v] token-major bf16
__device__ __align__(256) bf16 g_h0t[(size_t)BH * XR * C1I];   // conv0 out (silu) token-major bf16
__device__ __align__(256) bf16 g_pb [(size_t)BH * MC * SP];    // conv1 silu logits -> probs (in place)
__device__ __align__(256) bf16 g_w0r[C0O * K0];                // weights bf16, k = r*CIN + ci
__device__ __align__(256) bf16 g_w1r[C1O * K1];

// ---------------- low-level helpers ----------------
#define CP16(dst, src) asm volatile("cp.async.ca.shared.global [%0], [%1], 16;\n" \
    :: "r"((unsigned)__cvta_generic_to_shared(dst)), "l"(src))

__device__ __forceinline__ void ldsm4(unsigned* a, const void* p) {
    unsigned addr = (unsigned)__cvta_generic_to_shared(p);
    asm volatile("ldmatrix.sync.aligned.m8n8.x4.shared.b16 {%0,%1,%2,%3}, [%4];"
                 : "=r"(a[0]), "=r"(a[1]), "=r"(a[2]), "=r"(a[3]) : "r"(addr));
}
__device__ __forceinline__ void ldsm2(unsigned* b, const void* p) {
    unsigned addr = (unsigned)__cvta_generic_to_shared(p);
    asm volatile("ldmatrix.sync.aligned.m8n8.x2.shared.b16 {%0,%1}, [%2];"
                 : "=r"(b[0]), "=r"(b[1]) : "r"(addr));
}
__device__ __forceinline__ void ldsm2t(unsigned* b, const void* p) {
    unsigned addr = (unsigned)__cvta_generic_to_shared(p);
    asm volatile("ldmatrix.sync.aligned.m8n8.x2.trans.shared.b16 {%0,%1}, [%2];"
                 : "=r"(b[0]), "=r"(b[1]) : "r"(addr));
}
__device__ __forceinline__ void mma16(float* c, const unsigned* a, const unsigned* b) {
    asm volatile(
        "mma.sync.aligned.m16n8k16.row.col.f32.bf16.bf16.f32 "
        "{%0,%1,%2,%3},{%4,%5,%6,%7},{%8,%9},{%0,%1,%2,%3};\n"
        : "+f"(c[0]), "+f"(c[1]), "+f"(c[2]), "+f"(c[3])
        : "r"(a[0]), "r"(a[1]), "r"(a[2]), "r"(a[3]), "r"(b[0]), "r"(b[1]));
}

__device__ __forceinline__ unsigned f2key(float f) {
    unsigned u = __float_as_uint(f);
    return (u & 0x80000000u) ? ~u : (u | 0x80000000u);
}

__device__ int blk_scan_excl(int v, int& total) {
    __shared__ int wsum[8];
    __shared__ int tot;
    int tid = threadIdx.x, lane = tid & 31, w = tid >> 5;
    __syncthreads();
    int incl = v;
#pragma unroll
    for (int o = 1; o < 32; o <<= 1) {
        int y = __shfl_up_sync(0xffffffffu, incl, o);
        if (lane >= o) incl += y;
    }
    if (lane == 31) wsum[w] = incl;
    __syncthreads();
    if (tid == 0) {
        int run = 0;
#pragma unroll
        for (int i = 0; i < 8; i++) { int t = wsum[i]; wsum[i] = run; run += t; }
        tot = run;
    }
    __syncthreads();
    total = tot;
    return wsum[w] + incl - v;
}

__device__ void radix_topk(const float* __restrict__ sc, const int* __restrict__ idxmap,
                           int n, int k, unsigned& T, int& tieNeed) {
    __shared__ unsigned hist[256];
    __shared__ unsigned sh_pref;
    __shared__ int      sh_need;
    int tid = threadIdx.x;
    unsigned pref = 0; int need = k;
    for (int shift = 24; shift >= 0; shift -= 8) {
        __syncthreads();
        hist[tid] = 0;
        __syncthreads();
        for (int i = tid; i < n; i += 256) {
            int idx = idxmap ? idxmap[i] : i;
            unsigned key = f2key(sc[idx]);
            unsigned long long hi = (unsigned long long)key  >> (shift + 8);
            unsigned long long ph = (unsigned long long)pref >> (shift + 8);
            if (hi == ph) atomicAdd(&hist[(key >> shift) & 255], 1u);
        }
        __syncthreads();
        if (tid == 0) {
            unsigned cum = 0; int b = 255;
            for (; b > 0; b--) { unsigned h = hist[b]; if (cum + h >= (unsigned)need) break; cum += h; }
            sh_pref = pref | ((unsigned)b << shift);
            sh_need = need - (int)cum;
        }
        __syncthreads();
        pref = sh_pref; need = sh_need;
    }
    T = pref; tieNeed = need;
}

// ---------------- kernel: weight reorder (k = r*CIN + ci), to bf16 ----------------
__global__ void k_wprep(const float* __restrict__ w0, const float* __restrict__ w1) {
    int n0 = C0O * K0, n1 = C1O * K1;
    for (int e = blockIdx.x * blockDim.x + threadIdx.x; e < n0 + n1; e += gridDim.x * blockDim.x) {
        if (e < n0) {
            int o = e / K0, k = e % K0, r = k / C0I, i = k % C0I;
            g_w0r[e] = __float2bfloat16(w0[(o * C0I + i) * 3 + r]);
        } else {
            int e2 = e - n0;
            int o = e2 / K1, k = e2 % K1, r = k / C1I, i = k % C1I;
            g_w1r[e2] = __float2bfloat16(w1[(o * C1I + i) * 3 + r]);
        }
    }
}

// ---------------- kernel: zero conv pad rows ----------------
__global__ void k_zeropad() {
    int stride = gridDim.x * blockDim.x;
    int tid = blockIdx.x * blockDim.x + threadIdx.x;
    bf16 z = __float2bfloat16(0.f);
    for (int e = tid; e < BH * C0I; e += stride) {
        int bh = e / C0I, c = e % C0I;
        g_xt[((size_t)bh * XR + 0) * C0I + c] = z;
        g_xt[((size_t)bh * XR + SP + 1) * C0I + c] = z;
    }
    for (int e = tid; e < BH * C1I; e += stride) {
        int bh = e / C1I, c = e % C1I;
        g_h0t[((size_t)bh * XR + 0) * C1I + c] = z;
        g_h0t[((size_t)bh * XR + SP + 1) * C1I + c] = z;
    }
}

// ---------------- kernel: exact selection (both top-k's) ----------------
__global__ void __launch_bounds__(256) k_select(const float* __restrict__ scores) {
    int bh = blockIdx.x, tid = threadIdx.x;
    const float* sc = scores + (size_t)bh * S;

    unsigned T; int tieNeed;
    radix_topk(sc, nullptr, SEARCH, KTOP, T, tieNeed);

    int base = tid * 32;
    int eqc = 0;
    for (int j = 0; j < 32; j++) {
        int i = base + j;
        if (i < SEARCH && f2key(sc[i]) == T) eqc++;
    }
    int eqTot; int eqBase = blk_scan_excl(eqc, eqTot);
    unsigned mw = 0;
    {
        int run = eqBase;
        for (int j = 0; j < 32; j++) {
            int i = base + j;
            if (i >= SEARCH) { mw |= 1u << j; }
            else {
                unsigned key = f2key(sc[i]);
                if (key > T) mw |= 1u << j;
                else if (key == T) { if (run < tieNeed) mw |= 1u << j; run++; }
            }
        }
    }
    int selTot; int selBase = blk_scan_excl(__popc(mw), selTot);
    {
        int sr = selBase, nr = base - selBase;
        for (int j = 0; j < 32; j++) {
            int i = base + j;
            if ((mw >> j) & 1u) g_hhpos[bh * KEEP + (sr++)] = i;
            else                g_nonpos[bh * SP   + (nr++)] = i;
        }
    }
    __syncthreads();

    const int* npos = g_nonpos + bh * SP;
    unsigned T2; int tie2;
    radix_topk(sc, npos, SP, MC, T2, tie2);

    int eqc2 = 0;
    if (tid < SP / 32) {
        for (int j = 0; j < 32; j++) {
            int s = tid * 32 + j;
            if (f2key(sc[npos[s]]) == T2) eqc2++;
        }
    }
    int eqTot2; int eqB2 = blk_scan_excl(eqc2, eqTot2);
    unsigned mw2 = 0;
    if (tid < SP / 32) {
        int run2 = eqB2;
        for (int j = 0; j < 32; j++) {
            int s = tid * 32 + j;
            unsigned key = f2key(sc[npos[s]]);
            if (key > T2) mw2 |= 1u << j;
            else if (key == T2) { if (run2 < tie2) mw2 |= 1u << j; run2++; }
        }
    }
    int selTot2; int sb2 = blk_scan_excl(__popc(mw2), selTot2);
    if (tid < SP / 32) {
        int rr = sb2;
        for (int j = 0; j < 32; j++) {
            if ((mw2 >> j) & 1u) g_rpos[bh * MC + (rr++)] = npos[tid * 32 + j];
        }
    }
}

// ---------------- kernel: coalesced gather into token-major bf16 g_xt ----------------
__global__ void __launch_bounds__(256) k_gather(const float* __restrict__ Kin,
                                                const float* __restrict__ Vin) {
    __shared__ int pos[128];
    int bh = blockIdx.y, t0 = blockIdx.x * 128, tid = threadIdx.x;
    if (tid < 128) pos[tid] = g_nonpos[bh * SP + t0 + tid];
    __syncthreads();
    int w = tid >> 5, lane = tid & 31;
    const float4* Kb = (const float4*)(Kin + (size_t)bh * S * D);
    const float4* Vb = (const float4*)(Vin + (size_t)bh * S * D);
    for (int tt = w; tt < 128; tt += 8) {
        int p = pos[tt];
        __nv_bfloat162* X = (__nv_bfloat162*)(g_xt + ((size_t)bh * XR + t0 + 1 + tt) * C0I);
        float4 kk = Kb[(size_t)p * 32 + lane];
        float4 vv = Vb[(size_t)p * 32 + lane];
        X[lane * 2]          = __floats2bfloat162_rn(kk.x, kk.y);
        X[lane * 2 + 1]      = __floats2bfloat162_rn(kk.z, kk.w);
        X[64 + lane * 2]     = __floats2bfloat162_rn(vv.x, vv.y);
        X[64 + lane * 2 + 1] = __floats2bfloat162_rn(vv.z, vv.w);
    }
}

// ---------------- conv as TN bf16 GEMM: 128 threads, 64x64 warp tiles ----------------
// Y[o][t] = silu( sum_{k=(r,ci)} W[o][k] * X[t+r][ci] + bias[o] )
// Block tile 128(m) x 128(n), 4 warps in 2x2 grid of 64x64 tiles.
// Same smem layout / pipeline / barriers as the proven 256-thread version.
template <int CIN, int COUT, int KTOT, bool TO_H0>
__global__ void __launch_bounds__(128, 2) k_conv(const float* __restrict__ bias) {
    constexpr int LDA = 40;                       // bf16 row stride (80B): LDS conflict-free
    __shared__ bf16 SM[2][2][128 * LDA];          // [buf][A=0/B=1]
    const bf16* Wm = TO_H0 ? g_w0r : g_w1r;
    const bf16* Xs = TO_H0 ? g_xt  : g_h0t;
    int tid = threadIdx.x;
    int n0 = blockIdx.x * 128, m0 = blockIdx.y * 128, bh = blockIdx.z;
    const bf16* Xb = Xs + (size_t)bh * XR * CIN;
    int w = tid >> 5, lane = tid & 31;
    int wm = (w >> 1) * 64, wn = (w & 1) * 64;
    float acc[4][8][4] = {};

    auto LOAD = [&](int kt, int buf) {
        int r = kt / CIN, ci0 = kt % CIN;   // 32-wide chunk never crosses an r boundary
#pragma unroll
        for (int q = 0; q < 4; q++) {
            int e = tid + q * 128; int m = e >> 2, kp = (e & 3) * 8;
            CP16(&SM[buf][0][m * LDA + kp], Wm + (size_t)(m0 + m) * KTOT + kt + kp);
        }
#pragma unroll
        for (int q = 0; q < 4; q++) {
            int e = tid + q * 128; int n = e >> 2, kp = (e & 3) * 8;
            CP16(&SM[buf][1][n * LDA + kp], Xb + (size_t)(n0 + n + r) * CIN + ci0 + kp);
        }
    };
    auto COMP = [&](int buf) {
#pragma unroll
        for (int ks = 0; ks < 32; ks += 16) {
            unsigned a[4][4], b[8][2];
#pragma unroll
            for (int mi = 0; mi < 4; mi++) {
                int row = wm + mi * 16 + (lane & 15);
                int col = ks + ((lane >> 4) << 3);
                ldsm4(a[mi], &SM[buf][0][row * LDA + col]);
            }
#pragma unroll
            for (int nj = 0; nj < 4; nj++) {
                int row = wn + nj * 16 + (lane & 15);
                int col = ks + ((lane >> 4) << 3);
                unsigned t4[4];
                ldsm4(t4, &SM[buf][1][row * LDA + col]);
                b[nj * 2][0]     = t4[0]; b[nj * 2][1]     = t4[2];
                b[nj * 2 + 1][0] = t4[1]; b[nj * 2 + 1][1] = t4[3];
            }
#pragma unroll
            for (int mi = 0; mi < 4; mi++)
#pragma unroll
                for (int ni = 0; ni < 8; ni++) mma16(acc[mi][ni], a[mi], b[ni]);
        }
    };

    LOAD(0, 0);
    asm volatile("cp.async.commit_group;");
    int buf = 0;
    for (int kt = 0; kt < KTOT; kt += 32) {
        if (kt + 32 < KTOT) {
            LOAD(kt + 32, buf ^ 1);
            asm volatile("cp.async.commit_group;");
            asm volatile("cp.async.wait_group 1;");
        } else {
            asm volatile("cp.async.wait_group 0;");
        }
        __syncthreads();
        COMP(buf);
        __syncthreads();
        buf ^= 1;
    }

    if (TO_H0) {
        // stage C (token-major) through smem for coalesced bf16 stores
        constexpr int LDC = 136;                  // 272B rows: 16B-aligned, conflict-spread
        bf16* Cs = &SM[0][0][0];                  // 128*136 bf16 = 34816B <= 40960B
#pragma unroll
        for (int mi = 0; mi < 4; mi++)
#pragma unroll
            for (int ni = 0; ni < 8; ni++)
#pragma unroll
                for (int rg = 0; rg < 4; rg++) {
                    int ml = wm + mi * 16 + (lane >> 2) + ((rg >> 1) ? 8 : 0);
                    int nl = wn + ni * 8 + (lane & 3) * 2 + (rg & 1);
                    float v = acc[mi][ni][rg] + bias[m0 + ml];
                    v = v / (1.f + __expf(-v));
                    Cs[nl * LDC + ml] = __float2bfloat16(v);
                }
        __syncthreads();
        bf16* Yb = g_h0t + ((size_t)bh * XR + n0 + 1) * COUT + m0;
        for (int e = tid; e < 128 * 16; e += 128) {
            int t = e >> 4, ch = e & 15;
            *(uint4*)(Yb + (size_t)t * COUT + ch * 8) = *(const uint4*)(Cs + t * LDC + ch * 8);
        }
    } else {
        // direct bf16x2 stores of silu'd logits into g_pb [m][t]
        bf16* Yb = g_pb + (size_t)bh * (size_t)COUT * SP;
#pragma unroll
        for (int mi = 0; mi < 4; mi++)
#pragma unroll
            for (int ni = 0; ni < 8; ni++)
#pragma unroll
                for (int half = 0; half < 2; half++) {
                    int ml = wm + mi * 16 + (lane >> 2) + half * 8;
                    int t  = n0 + wn + ni * 8 + (lane & 3) * 2;
                    float v0 = acc[mi][ni][half * 2 + 0] + bias[m0 + ml];
                    float v1 = acc[mi][ni][half * 2 + 1] + bias[m0 + ml];
                    v0 = v0 / (1.f + __expf(-v0));
                    v1 = v1 / (1.f + __expf(-v1));
                    *(__nv_bfloat162*)(Yb + (size_t)(m0 + ml) * SP + t) =
                        __floats2bfloat162_rn(v0, v1);
                }
    }
}

// ---------------- row softmax in place on bf16 logits ----------------
__device__ float blk_max256(float v) {
    __shared__ float sh[8]; __shared__ float res;
    int tid = threadIdx.x;
    __syncthreads();
#pragma unroll
    for (int o = 16; o; o >>= 1) v = fmaxf(v, __shfl_xor_sync(0xffffffffu, v, o));
    if ((tid & 31) == 0) sh[tid >> 5] = v;
    __syncthreads();
    if (tid == 0) { float m = sh[0]; for (int i = 1; i < 8; i++) m = fmaxf(m, sh[i]); res = m; }
    __syncthreads();
    return res;
}
__device__ float blk_sum256(float v) {
    __shared__ float sh[8]; __shared__ float res;
    int tid = threadIdx.x;
    __syncthreads();
#pragma unroll
    for (int o = 16; o; o >>= 1) v += __shfl_xor_sync(0xffffffffu, v, o);
    if ((tid & 31) == 0) sh[tid >> 5] = v;
    __syncthreads();
    if (tid == 0) { float s = 0; for (int i = 0; i < 8; i++) s += sh[i]; res = s; }
    __syncthreads();
    return res;
}
__global__ void __launch_bounds__(256) k_softmax() {
    int bh = blockIdx.y, m = blockIdx.x, tid = threadIdx.x;
    bf16* row = g_pb + ((size_t)bh * MC + m) * SP;
    float v[31]; float mx = -1e30f;
#pragma unroll
    for (int q = 0; q < 31; q++) { v[q] = __bfloat162float(row[tid + q * 256]); mx = fmaxf(mx, v[q]); }
    mx = blk_max256(mx);
    float s = 0.f;
#pragma unroll
    for (int q = 0; q < 31; q++) { float e = __expf(v[q] - mx); v[q] = e; s += e; }
    s = blk_sum256(s);
    float inv = 1.f / s;
#pragma unroll
    for (int q = 0; q < 31; q++) row[tid + q * 256] = __float2bfloat16(v[q] * inv);
}

// ---------------- merge: bf16 TN GEMM + exact fp32 residual (proven structure) ----------------
__global__ void __launch_bounds__(256, 2) k_merge(const float* __restrict__ Kin,
                                                  const float* __restrict__ Vin,
                                                  const float* __restrict__ nrmp,
                                                  float* __restrict__ out) {
    constexpr int LDA = 40;
    constexpr int LDB = 136;
    __shared__ bf16 SA[2][128 * LDA];
    __shared__ bf16 SB[2][32 * LDB];
    int tid = threadIdx.x;
    int n0 = blockIdx.x * 128, m0 = blockIdx.y * 128, bh = blockIdx.z;
    const bf16* A  = g_pb + (size_t)bh * MC * SP;
    const bf16* Xb = g_xt + (size_t)bh * XR * C0I;
    int w = tid >> 5, lane = tid & 31;
    int wm = (w >> 2) * 64, wn = (w & 3) * 32;
    float acc[4][4][4] = {};

    auto LOAD = [&](int kt, int buf) {
#pragma unroll
        for (int q = 0; q < 2; q++) {
            int e = tid + q * 256; int m = e >> 2, kp = (e & 3) * 8;
            CP16(&SA[buf][m * LDA + kp], A + (size_t)(m0 + m) * SP + kt + kp);
        }
#pragma unroll
        for (int q = 0; q < 2; q++) {
            int e = tid + q * 256; int k = e >> 4, ch = e & 15;
            CP16(&SB[buf][k * LDB + ch * 8], Xb + (size_t)(kt + k + 1) * C0I + n0 + ch * 8);
        }
    };
    auto COMP = [&](int buf) {
#pragma unroll
        for (int ks = 0; ks < 32; ks += 16) {
            unsigned a[4][4], b[4][2];
#pragma unroll
            for (int mi = 0; mi < 4; mi++) {
                int row = wm + mi * 16 + (lane & 15);
                int col = ks + ((lane >> 4) << 3);
                ldsm4(a[mi], &SA[buf][row * LDA + col]);
            }
#pragma unroll
            for (int ni = 0; ni < 4; ni++) {
                int row = ks + (lane & 15);
                ldsm2t(b[ni], &SB[buf][row * LDB + wn + ni * 8]);
            }
#pragma unroll
            for (int mi = 0; mi < 4; mi++)
#pragma unroll
                for (int ni = 0; ni < 4; ni++) mma16(acc[mi][ni], a[mi], b[ni]);
        }
    };

    LOAD(0, 0);
    asm volatile("cp.async.commit_group;");
    int buf = 0;
    for (int kt = 0; kt < SP; kt += 32) {
        if (kt + 32 < SP) {
            LOAD(kt + 32, buf ^ 1);
            asm volatile("cp.async.commit_group;");
            asm volatile("cp.async.wait_group 1;");
        } else {
            asm volatile("cp.async.wait_group 0;");
        }
        __syncthreads();
        COMP(buf);
        __syncthreads();
        buf ^= 1;
    }

    float nrm = nrmp[0], rn = 1.f - nrm;
#pragma unroll
    for (int mi = 0; mi < 4; mi++)
#pragma unroll
        for (int ni = 0; ni < 4; ni++)
#pragma unroll
            for (int rg = 0; rg < 4; rg++) {
                int ml = wm + mi * 16 + (lane >> 2) + ((rg >> 1) ? 8 : 0);
                int nl = wn + ni * 8 + (lane & 3) * 2 + (rg & 1);
                int m = m0 + ml, n = n0 + nl;
                int rp = g_rpos[bh * MC + m];
                float res; float* dst;
                if (n < 128) {
                    res = Kin[((size_t)bh * S + rp) * D + n];
                    dst = out + ((size_t)bh * 512 + 256 + m) * 128 + n;
                } else {
                    res = Vin[((size_t)bh * S + rp) * D + n - 128];
                    dst = out + VOFF + ((size_t)bh * 512 + 256 + m) * 128 + n - 128;
                }
                *dst = nrm * acc[mi][ni][rg] + rn * res;
            }
}

// ---------------- exact hh gather into output rows [0,256) ----------------
__global__ void __launch_bounds__(256) k_hhcopy(const float* __restrict__ Kin,
                                                const float* __restrict__ Vin,
                                                float* __restrict__ out) {
    int bh = blockIdx.x, tid = threadIdx.x;
    const float* Kb = Kin + (size_t)bh * S * D;
    const float* Vb = Vin + (size_t)bh * S * D;
    float* ok = out + (size_t)bh * 512 * 128;
    float* ov = out + VOFF + (size_t)bh * 512 * 128;
    for (int e = tid; e < KEEP * D; e += 256) {
        int j = e >> 7, d = e & 127;
        int pos = g_hhpos[bh * KEEP + j];
        ok[(size_t)j * 128 + d] = Kb[(size_t)pos * D + d];
        ov[(size_t)j * 128 + d] = Vb[(size_t)pos * D + d];
    }
}

// ---------------- launch ----------------
extern "C" void kernel_launch(void* const* d_in, const int* in_sizes, int n_in,
                              void* d_out, int out_size) {
    const float* Kin = (const float*)d_in[0];
    const float* Vin = (const float*)d_in[1];
    const float* sc  = (const float*)d_in[2];
    const float* w0  = (const float*)d_in[3];
    const float* b0  = (const float*)d_in[4];
    const float* w1  = (const float*)d_in[5];
    const float* b1  = (const float*)d_in[6];
    const float* nrm = (const float*)d_in[7];
    float* out = (float*)d_out;
    (void)in_sizes; (void)n_in; (void)out_size;

    k_wprep<<<768, 256>>>(w0, w1);
    k_zeropad<<<128, 256>>>();
    k_select<<<BH, 256>>>(sc);
    {
        dim3 g(SP / 128, BH);
        k_gather<<<g, 256>>>(Kin, Vin);
    }
    {
        dim3 g0(SP / 128, C0O / 128, BH);          // 62 x 4 x 64
        k_conv<C0I, C0O, K0, true><<<g0, 128>>>(b0);
        dim3 g1(SP / 128, C1O / 128, BH);          // 62 x 2 x 64
        k_conv<C1I, C1O, K1, false><<<g1, 128>>>(b1);
    }
    {
        dim3 gs(MC, BH);
        k_softmax<<<gs, 256>>>();
    }
    {
        dim3 gm(2, 2, BH);
        k_merge<<<gm, 256>>>(Kin, Vin, nrm, out);
    }
    k_hhcopy<<<BH, 256>>>(Kin, Vin, out);
}